// round 4
// baseline (speedup 1.0000x reference)
#include <cuda_runtime.h>
#include <cstdint>
#include <cstddef>
#include <cfloat>

#define N_NODES 50000
#define DIM 256
#define N_EDGES 800000
#define N_LAYERS 5

// ---------------- device scratch (allocation-free: .bss globals) ----------------
__device__ float g_bufA0[N_NODES * DIM];
__device__ float g_bufA1[N_NODES * DIM];
__device__ float g_bufP0[N_NODES * DIM];
__device__ float g_bufP1[N_NODES * DIM];
__device__ float g_aggA[N_NODES * DIM];
__device__ float g_aggP[N_NODES * DIM];
__device__ int   g_degA[N_NODES];
__device__ int   g_degP[N_NODES];
__device__ int   g_offA[N_NODES + 1];
__device__ int   g_offP[N_NODES + 1];
__device__ int   g_curA[N_NODES];
__device__ int   g_curP[N_NODES];
__device__ int   g_csrA[N_EDGES];
__device__ int   g_csrP[N_EDGES];
__device__ float g_nrmA[2][N_NODES];   // sumsq -> invnorm, ping-pong by layer
__device__ float g_nrmP[2][N_NODES];

// ---------------- CSR build: degree count (both directions, grid.y=2) ----------------
__global__ void deg2_kernel(const int* __restrict__ dstP, int* __restrict__ degP,
                            const int* __restrict__ dstA, int* __restrict__ degA, int E) {
    int e = blockIdx.x * blockDim.x + threadIdx.x;
    if (e < E) {
        if (blockIdx.y == 0) atomicAdd(&degP[dstP[e]], 1);
        else                 atomicAdd(&degA[dstA[e]], 1);
    }
}

// ---------------- CSR build: coarsened single-block scan, grid.x = 2 ----------------
__global__ void scan2_kernel(const int* __restrict__ d0, int* __restrict__ o0,
                             const int* __restrict__ d1, int* __restrict__ o1, int n) {
    const int* deg = blockIdx.x ? d1 : d0;
    int*       off = blockIdx.x ? o1 : o0;
    const int tid = threadIdx.x;
    const int nthr = blockDim.x;                 // 1024
    const int chunk = (n + nthr - 1) / nthr;     // 49
    const int s = tid * chunk;
    const int e = min(s + chunk, n);

    int sum = 0;
    for (int i = s; i < e; i++) sum += deg[i];

    __shared__ int wsum[32];
    int x = sum;
    const int lane = tid & 31, wid = tid >> 5;
#pragma unroll
    for (int o = 1; o < 32; o <<= 1) {
        int y = __shfl_up_sync(0xFFFFFFFFu, x, o);
        if (lane >= o) x += y;
    }
    if (lane == 31) wsum[wid] = x;
    __syncthreads();
    if (tid < 32) {
        int w = wsum[tid];
#pragma unroll
        for (int o = 1; o < 32; o <<= 1) {
            int y = __shfl_up_sync(0xFFFFFFFFu, w, o);
            if (tid >= o) w += y;
        }
        wsum[tid] = w;
    }
    __syncthreads();
    int run = x - sum + (wid ? wsum[wid - 1] : 0);   // exclusive prefix of this chunk
    for (int i = s; i < e; i++) { int v = deg[i]; off[i] = run; run += v; }
    if (tid == 0) off[n] = wsum[31];
}

// ---------------- CSR build: slot fill (both directions, grid.y=2) ----------------
__global__ void fill2_kernel(const int* __restrict__ eap, int* __restrict__ curP, int* __restrict__ csrP,
                             const int* __restrict__ epa, int* __restrict__ curA, int* __restrict__ csrA,
                             int E) {
    int e = blockIdx.x * blockDim.x + threadIdx.x;
    if (e < E) {
        if (blockIdx.y == 0) {
            int slot = atomicAdd(&curP[eap[E + e]], 1);
            csrP[slot] = eap[e];
        } else {
            int slot = atomicAdd(&curA[epa[E + e]], 1);
            csrA[slot] = epa[e];
        }
    }
}

// ---------------- gather: agg[dst] = mean over neighbors of f(x[src]) ----------------
// NORM=true: f(v) = invn[src] * relu(v)  (== relu(l2norm(x)) row)
template <bool NORM>
__global__ void gather_kernel(const float* __restrict__ x, const float* __restrict__ invn,
                              const int* __restrict__ off, const int* __restrict__ csr,
                              float* __restrict__ agg, int n) {
    int row = blockIdx.x * (blockDim.x >> 5) + (threadIdx.x >> 5);
    if (row >= n) return;
    const int lane = threadIdx.x & 31;
    const int beg = off[row], end = off[row + 1];

    float4 s0 = make_float4(0.f, 0.f, 0.f, 0.f);
    float4 s1 = make_float4(0.f, 0.f, 0.f, 0.f);
    for (int e = beg; e < end; e++) {
        int i0 = csr[e];
        const float4* p0 = reinterpret_cast<const float4*>(x + (size_t)i0 * DIM);
        float4 a = p0[lane], b = p0[lane + 32];
        if (NORM) {
            float w = invn[i0];
            s0.x = fmaf(fmaxf(a.x, 0.f), w, s0.x); s0.y = fmaf(fmaxf(a.y, 0.f), w, s0.y);
            s0.z = fmaf(fmaxf(a.z, 0.f), w, s0.z); s0.w = fmaf(fmaxf(a.w, 0.f), w, s0.w);
            s1.x = fmaf(fmaxf(b.x, 0.f), w, s1.x); s1.y = fmaf(fmaxf(b.y, 0.f), w, s1.y);
            s1.z = fmaf(fmaxf(b.z, 0.f), w, s1.z); s1.w = fmaf(fmaxf(b.w, 0.f), w, s1.w);
        } else {
            s0.x += a.x; s0.y += a.y; s0.z += a.z; s0.w += a.w;
            s1.x += b.x; s1.y += b.y; s1.z += b.z; s1.w += b.w;
        }
    }
    const float inv = 1.0f / fmaxf((float)(end - beg), 1.0f);
    s0.x *= inv; s0.y *= inv; s0.z *= inv; s0.w *= inv;
    s1.x *= inv; s1.y *= inv; s1.z *= inv; s1.w *= inv;
    float4* o = reinterpret_cast<float4*>(agg + (size_t)row * DIM);
    o[lane] = s0;
    o[lane + 32] = s1;
}

// ---------------- tf32 tensor-core fused dual GEMM ----------------
// out = agg @ Wl^T + f(self) @ Wr^T + b, f(v) = invnSelf[row]*relu(v) (or identity).
// If sqOut != null, also accumulate per-row sum of squares of out (for next layer's norm).
// BM=128, BN=128, BK=16, 256 threads = 8 warps, warp tile 32(m) x 64(n).

__device__ __forceinline__ void cp_async16(void* smem, const void* gmem, bool pred) {
    uint32_t s = (uint32_t)__cvta_generic_to_shared(smem);
    int sz = pred ? 16 : 0;
    asm volatile("cp.async.cg.shared.global [%0], [%1], 16, %2;"
                 :: "r"(s), "l"(gmem), "r"(sz));
}

__device__ __forceinline__ uint32_t f2tf32(float f) {
    uint32_t r;
    asm("cvt.rna.tf32.f32 %0, %1;" : "=r"(r) : "f"(f));
    return r;
}

#define LDA 20   // 16 used + 4 pad: conflict-free fragment loads

__global__ __launch_bounds__(256, 2)
void gemm_tc_kernel(const float* __restrict__ Aagg,
                    const float* __restrict__ Aself,
                    const float* __restrict__ invnSelf,   // null => identity self transform
                    const float* __restrict__ Wl, const float* __restrict__ Wr,
                    const float* __restrict__ bias,
                    float* __restrict__ out,
                    float* __restrict__ sqOut,            // null => skip sumsq accumulation
                    int M) {
    __shared__ float As[2][128][LDA];
    __shared__ float Bs[2][128][LDA];

    const int bm = blockIdx.y * 128;
    const int bn = blockIdx.x * 128;
    const int t = threadIdx.x;
    const int wid = t >> 5;
    const int lane = t & 31;
    const int wm = wid & 3;
    const int wn = wid >> 2;
    const int gid = lane >> 2;
    const int tig = lane & 3;

    // self-phase row transform params (identity when invnSelf == null)
    const float nlim = invnSelf ? 0.0f : -FLT_MAX;
    float rn[2][2];
#pragma unroll
    for (int mi = 0; mi < 2; mi++) {
        int r = bm + wm * 32 + mi * 16 + gid;
        rn[mi][0] = (invnSelf && r < M)     ? invnSelf[r]     : 1.0f;
        rn[mi][1] = (invnSelf && r + 8 < M) ? invnSelf[r + 8] : 1.0f;
    }

    float acc[2][8][4];
#pragma unroll
    for (int mi = 0; mi < 2; mi++)
#pragma unroll
        for (int ni = 0; ni < 8; ni++)
#pragma unroll
            for (int j = 0; j < 4; j++) acc[mi][ni][j] = 0.0f;

    auto load_tile = [&](int stage, int kt) {
        const int phase = kt >> 4;
        const int kloc = (kt & 15) << 4;
        const float* Ap = phase ? Aself : Aagg;
        const float* Bp = phase ? Wr : Wl;
#pragma unroll
        for (int i = 0; i < 2; i++) {
            int c = t + i * 256;
            int row = c >> 2;
            int seg = c & 3;
            int gr = bm + row;
            cp_async16(&As[stage][row][seg * 4],
                       Ap + (size_t)gr * DIM + kloc + seg * 4, gr < M);
            cp_async16(&Bs[stage][row][seg * 4],
                       Bp + (size_t)(bn + row) * DIM + kloc + seg * 4, true);
        }
        asm volatile("cp.async.commit_group;" ::: "memory");
    };

    load_tile(0, 0);

#pragma unroll 1
    for (int kt = 0; kt < 32; kt++) {
        const int s = kt & 1;
        const bool ph = (kt >= 16);   // self phase -> apply relu+invn transform
        if (kt + 1 < 32) {
            load_tile(1 - s, kt + 1);
            asm volatile("cp.async.wait_group 1;" ::: "memory");
        } else {
            asm volatile("cp.async.wait_group 0;" ::: "memory");
        }
        __syncthreads();

#pragma unroll
        for (int kk = 0; kk < 2; kk++) {
            const int c0 = kk * 8 + tig;
            uint32_t aR[2][4];
#pragma unroll
            for (int mi = 0; mi < 2; mi++) {
                int r0 = wm * 32 + mi * 16 + gid;
                float v0 = As[s][r0][c0];
                float v1 = As[s][r0 + 8][c0];
                float v2 = As[s][r0][c0 + 4];
                float v3 = As[s][r0 + 8][c0 + 4];
                if (ph) {
                    v0 = fmaxf(v0, nlim) * rn[mi][0];
                    v1 = fmaxf(v1, nlim) * rn[mi][1];
                    v2 = fmaxf(v2, nlim) * rn[mi][0];
                    v3 = fmaxf(v3, nlim) * rn[mi][1];
                }
                aR[mi][0] = f2tf32(v0);
                aR[mi][1] = f2tf32(v1);
                aR[mi][2] = f2tf32(v2);
                aR[mi][3] = f2tf32(v3);
            }
            uint32_t bR[8][2];
#pragma unroll
            for (int ni = 0; ni < 8; ni++) {
                int n0 = wn * 64 + ni * 8 + gid;
                bR[ni][0] = f2tf32(Bs[s][n0][c0]);
                bR[ni][1] = f2tf32(Bs[s][n0][c0 + 4]);
            }
#pragma unroll
            for (int mi = 0; mi < 2; mi++)
#pragma unroll
                for (int ni = 0; ni < 8; ni++) {
                    asm volatile(
                        "mma.sync.aligned.m16n8k8.row.col.f32.tf32.tf32.f32 "
                        "{%0,%1,%2,%3}, {%4,%5,%6,%7}, {%8,%9}, {%0,%1,%2,%3};"
                        : "+f"(acc[mi][ni][0]), "+f"(acc[mi][ni][1]),
                          "+f"(acc[mi][ni][2]), "+f"(acc[mi][ni][3])
                        : "r"(aR[mi][0]), "r"(aR[mi][1]), "r"(aR[mi][2]), "r"(aR[mi][3]),
                          "r"(bR[ni][0]), "r"(bR[ni][1]));
                }
        }
        __syncthreads();
    }

    // ---- epilogue: bias add + store; optionally accumulate row sum-of-squares
    float ps[2][2] = {{0.f, 0.f}, {0.f, 0.f}};
#pragma unroll
    for (int ni = 0; ni < 8; ni++) {
        int col = bn + wn * 64 + ni * 8 + 2 * tig;
        float bx = bias[col], by = bias[col + 1];
#pragma unroll
        for (int mi = 0; mi < 2; mi++) {
            int r0 = bm + wm * 32 + mi * 16 + gid;
            if (r0 < M) {
                float ox = acc[mi][ni][0] + bx;
                float oy = acc[mi][ni][1] + by;
                ps[mi][0] = fmaf(ox, ox, fmaf(oy, oy, ps[mi][0]));
                *reinterpret_cast<float2*>(out + (size_t)r0 * DIM + col) = make_float2(ox, oy);
            }
            if (r0 + 8 < M) {
                float ox = acc[mi][ni][2] + bx;
                float oy = acc[mi][ni][3] + by;
                ps[mi][1] = fmaf(ox, ox, fmaf(oy, oy, ps[mi][1]));
                *reinterpret_cast<float2*>(out + (size_t)(r0 + 8) * DIM + col) = make_float2(ox, oy);
            }
        }
    }
    if (sqOut) {
        // reduce within quad (lanes gid*4 + tig share the same rows)
#pragma unroll
        for (int mi = 0; mi < 2; mi++)
#pragma unroll
            for (int h = 0; h < 2; h++) {
                float v = ps[mi][h];
                v += __shfl_xor_sync(0xFFFFFFFFu, v, 1);
                v += __shfl_xor_sync(0xFFFFFFFFu, v, 2);
                if (tig == 0) {
                    int r = bm + wm * 32 + mi * 16 + gid + h * 8;
                    if (r < M)
                        asm volatile("red.global.add.f32 [%0], %1;"
                                     :: "l"(sqOut + r), "f"(v) : "memory");
                }
            }
    }
}

// ---------------- finalize: sumsq -> inverse norm ----------------
__global__ void invnorm_kernel(float* __restrict__ sqP, float* __restrict__ sqA, int n) {
    int i = blockIdx.x * blockDim.x + threadIdx.x;
    if (i < n) {
        sqP[i] = 1.0f / fmaxf(sqrtf(sqP[i]), 1e-12f);
        sqA[i] = 1.0f / fmaxf(sqrtf(sqA[i]), 1e-12f);
    }
}

// ---------------- host orchestration ----------------
extern "C" void kernel_launch(void* const* d_in, const int* in_sizes, int n_in,
                              void* d_out, int out_size) {
    (void)in_sizes; (void)n_in; (void)out_size;
    const float* xa_in = (const float*)d_in[0];
    const float* xp_in = (const float*)d_in[1];
    const float* Wl    = (const float*)d_in[2];
    const float* bl    = (const float*)d_in[3];
    const float* Wr    = (const float*)d_in[4];
    const int*   e_ap  = (const int*)d_in[5];
    const int*   e_pa  = (const int*)d_in[6];
    float* out = (float*)d_out;

    float *bufA[2], *bufP[2], *aggA, *aggP, *nrmA, *nrmP;
    int *degA, *degP, *offA, *offP, *curA, *curP, *csrA, *csrP;
    cudaGetSymbolAddress((void**)&bufA[0], g_bufA0);
    cudaGetSymbolAddress((void**)&bufA[1], g_bufA1);
    cudaGetSymbolAddress((void**)&bufP[0], g_bufP0);
    cudaGetSymbolAddress((void**)&bufP[1], g_bufP1);
    cudaGetSymbolAddress((void**)&aggA, g_aggA);
    cudaGetSymbolAddress((void**)&aggP, g_aggP);
    cudaGetSymbolAddress((void**)&nrmA, g_nrmA);
    cudaGetSymbolAddress((void**)&nrmP, g_nrmP);
    cudaGetSymbolAddress((void**)&degA, g_degA);
    cudaGetSymbolAddress((void**)&degP, g_degP);
    cudaGetSymbolAddress((void**)&offA, g_offA);
    cudaGetSymbolAddress((void**)&offP, g_offP);
    cudaGetSymbolAddress((void**)&curA, g_curA);
    cudaGetSymbolAddress((void**)&curP, g_curP);
    cudaGetSymbolAddress((void**)&csrA, g_csrA);
    cudaGetSymbolAddress((void**)&csrP, g_csrP);

    // ---- CSR build (once per launch) ----
    cudaMemsetAsync(degA, 0, N_NODES * sizeof(int));
    cudaMemsetAsync(degP, 0, N_NODES * sizeof(int));
    {
        dim3 g((N_EDGES + 255) / 256, 2);
        deg2_kernel<<<g, 256>>>(e_ap + N_EDGES, degP, e_pa + N_EDGES, degA, N_EDGES);
    }
    scan2_kernel<<<2, 1024>>>(degP, offP, degA, offA, N_NODES);
    cudaMemcpyAsync(curP, offP, N_NODES * sizeof(int), cudaMemcpyDeviceToDevice);
    cudaMemcpyAsync(curA, offA, N_NODES * sizeof(int), cudaMemcpyDeviceToDevice);
    {
        dim3 g((N_EDGES + 255) / 256, 2);
        fill2_kernel<<<g, 256>>>(e_ap, curP, csrP, e_pa, curA, csrA, N_EDGES);
    }

    const float* inA = xa_in;
    const float* inP = xp_in;
    const float* invA = nullptr;   // invnorm of inA rows (null at layer 0)
    const float* invP = nullptr;

    dim3 gGrid(DIM / 128, (N_NODES + 127) / 128);   // (2, 391)
    int warpBlocks = (N_NODES + 7) / 8;

    for (int l = 0; l < N_LAYERS; l++) {
        const bool last = (l == N_LAYERS - 1);
        float* outA = last ? out : bufA[l & 1];
        float* outP = last ? out + (size_t)N_NODES * DIM : bufP[l & 1];
        float* sqP = nrmP + (l & 1) * N_NODES;   // sumsq accumulators for this layer's outputs
        float* sqA = nrmA + (l & 1) * N_NODES;

        if (invA)
            gather_kernel<true><<<warpBlocks, 256>>>(inA, invA, offP, csrP, aggP, N_NODES);
        else
            gather_kernel<false><<<warpBlocks, 256>>>(inA, nullptr, offP, csrP, aggP, N_NODES);
        if (invP)
            gather_kernel<true><<<warpBlocks, 256>>>(inP, invP, offA, csrA, aggA, N_NODES);
        else
            gather_kernel<false><<<warpBlocks, 256>>>(inP, nullptr, offA, csrA, aggA, N_NODES);

        if (!last) {
            cudaMemsetAsync(sqP, 0, N_NODES * sizeof(float));
            cudaMemsetAsync(sqA, 0, N_NODES * sizeof(float));
        }

        const float* Wl_p = Wl + ((size_t)l * 2 + 0) * DIM * DIM;
        const float* Wr_p = Wr + ((size_t)l * 2 + 0) * DIM * DIM;
        const float* bl_p = bl + ((size_t)l * 2 + 0) * DIM;
        const float* Wl_a = Wl + ((size_t)l * 2 + 1) * DIM * DIM;
        const float* Wr_a = Wr + ((size_t)l * 2 + 1) * DIM * DIM;
        const float* bl_a = bl + ((size_t)l * 2 + 1) * DIM;

        gemm_tc_kernel<<<gGrid, 256>>>(aggP, inP, invP, Wl_p, Wr_p, bl_p,
                                       outP, last ? nullptr : sqP, N_NODES);
        gemm_tc_kernel<<<gGrid, 256>>>(aggA, inA, invA, Wl_a, Wr_a, bl_a,
                                       outA, last ? nullptr : sqA, N_NODES);

        if (!last)
            invnorm_kernel<<<(N_NODES + 255) / 256, 256>>>(sqP, sqA, N_NODES);

        inA = outA; inP = outP;
        invA = sqA; invP = sqP;   // now hold inverse norms (after invnorm_kernel)
    }
}

// round 5
// speedup vs baseline: 1.1309x; 1.1309x over previous
#include <cuda_runtime.h>
#include <cstdint>
#include <cstddef>

#define N_NODES 50000
#define DIM 256
#define N_EDGES 800000
#define N_LAYERS 5

// ---------------- device scratch (allocation-free: .bss globals) ----------------
__device__ float g_bufA0[N_NODES * DIM];
__device__ float g_bufA1[N_NODES * DIM];
__device__ float g_bufP0[N_NODES * DIM];
__device__ float g_bufP1[N_NODES * DIM];
__device__ float g_aggA[N_NODES * DIM];
__device__ float g_aggP[N_NODES * DIM];
__device__ int   g_degA[N_NODES];
__device__ int   g_degP[N_NODES];
__device__ int   g_offA[N_NODES + 1];
__device__ int   g_offP[N_NODES + 1];
__device__ int   g_curA[N_NODES];
__device__ int   g_curP[N_NODES];
__device__ int   g_csrA[N_EDGES];
__device__ int   g_csrP[N_EDGES];

// ---------------- CSR build: degree count (both directions, grid.y=2) ----------------
__global__ void deg2_kernel(const int* __restrict__ dstP, int* __restrict__ degP,
                            const int* __restrict__ dstA, int* __restrict__ degA, int E) {
    int e = blockIdx.x * blockDim.x + threadIdx.x;
    if (e < E) {
        if (blockIdx.y == 0) atomicAdd(&degP[dstP[e]], 1);
        else                 atomicAdd(&degA[dstA[e]], 1);
    }
}

// ---------------- CSR build: coarsened scan, one block per direction ----------------
__global__ void scan2_kernel(const int* __restrict__ d0, int* __restrict__ o0,
                             const int* __restrict__ d1, int* __restrict__ o1, int n) {
    const int* deg = blockIdx.x ? d1 : d0;
    int*       off = blockIdx.x ? o1 : o0;
    const int tid = threadIdx.x;
    const int nthr = blockDim.x;                 // 1024
    const int chunk = (n + nthr - 1) / nthr;
    const int s = tid * chunk;
    const int e = min(s + chunk, n);

    int sum = 0;
    for (int i = s; i < e; i++) sum += deg[i];

    __shared__ int wsum[32];
    int x = sum;
    const int lane = tid & 31, wid = tid >> 5;
#pragma unroll
    for (int o = 1; o < 32; o <<= 1) {
        int y = __shfl_up_sync(0xFFFFFFFFu, x, o);
        if (lane >= o) x += y;
    }
    if (lane == 31) wsum[wid] = x;
    __syncthreads();
    if (tid < 32) {
        int w = wsum[tid];
#pragma unroll
        for (int o = 1; o < 32; o <<= 1) {
            int y = __shfl_up_sync(0xFFFFFFFFu, w, o);
            if (tid >= o) w += y;
        }
        wsum[tid] = w;
    }
    __syncthreads();
    int run = x - sum + (wid ? wsum[wid - 1] : 0);
    for (int i = s; i < e; i++) { int v = deg[i]; off[i] = run; run += v; }
    if (tid == 0) off[n] = wsum[31];
}

// ---------------- CSR build: slot fill (both directions, grid.y=2) ----------------
__global__ void fill2_kernel(const int* __restrict__ eap, int* __restrict__ curP, int* __restrict__ csrP,
                             const int* __restrict__ epa, int* __restrict__ curA, int* __restrict__ csrA,
                             int E) {
    int e = blockIdx.x * blockDim.x + threadIdx.x;
    if (e < E) {
        if (blockIdx.y == 0) {
            int slot = atomicAdd(&curP[eap[E + e]], 1);
            csrP[slot] = eap[e];
        } else {
            int slot = atomicAdd(&curA[epa[E + e]], 1);
            csrA[slot] = epa[e];
        }
    }
}

// ---------------- gather (both directions in one launch via grid.y) ----------------
// agg[dst] = mean over neighbors of x[src]; warp per row, 2-edge unroll for MLP
__global__ void gather2_kernel(const float* __restrict__ xA, const int* __restrict__ offP,
                               const int* __restrict__ csrP, float* __restrict__ aggP,
                               const float* __restrict__ xP, const int* __restrict__ offA,
                               const int* __restrict__ csrA, float* __restrict__ aggA,
                               int n) {
    int row = blockIdx.x * (blockDim.x >> 5) + (threadIdx.x >> 5);
    if (row >= n) return;
    const int lane = threadIdx.x & 31;
    const float* x;
    const int *off, *csr;
    float* agg;
    if (blockIdx.y == 0) { x = xA; off = offP; csr = csrP; agg = aggP; }
    else                 { x = xP; off = offA; csr = csrA; agg = aggA; }
    const int beg = off[row], end = off[row + 1];

    float4 s0 = make_float4(0.f, 0.f, 0.f, 0.f);
    float4 s1 = make_float4(0.f, 0.f, 0.f, 0.f);
    int e = beg;
    for (; e + 1 < end; e += 2) {
        int i0 = csr[e], i1 = csr[e + 1];
        const float4* p0 = reinterpret_cast<const float4*>(x + (size_t)i0 * DIM);
        const float4* p1 = reinterpret_cast<const float4*>(x + (size_t)i1 * DIM);
        float4 a = p0[lane], b = p0[lane + 32];
        float4 c = p1[lane], d = p1[lane + 32];
        s0.x += a.x; s0.y += a.y; s0.z += a.z; s0.w += a.w;
        s1.x += b.x; s1.y += b.y; s1.z += b.z; s1.w += b.w;
        s0.x += c.x; s0.y += c.y; s0.z += c.z; s0.w += c.w;
        s1.x += d.x; s1.y += d.y; s1.z += d.z; s1.w += d.w;
    }
    if (e < end) {
        const float4* p0 = reinterpret_cast<const float4*>(x + (size_t)csr[e] * DIM);
        float4 a = p0[lane], b = p0[lane + 32];
        s0.x += a.x; s0.y += a.y; s0.z += a.z; s0.w += a.w;
        s1.x += b.x; s1.y += b.y; s1.z += b.z; s1.w += b.w;
    }
    const float inv = 1.0f / fmaxf((float)(end - beg), 1.0f);
    s0.x *= inv; s0.y *= inv; s0.z *= inv; s0.w *= inv;
    s1.x *= inv; s1.y *= inv; s1.z *= inv; s1.w *= inv;
    float4* o = reinterpret_cast<float4*>(agg + (size_t)row * DIM);
    o[lane] = s0;
    o[lane + 32] = s1;
}

// ---------------- tf32 tensor-core fused dual GEMM ----------------
// out = agg @ Wl^T + self @ Wr^T + b
// BM=128, BN=128, BK=16, 256 threads = 8 warps, warp tile 32(m) x 64(n).

__device__ __forceinline__ void cp_async16(void* smem, const void* gmem, bool pred) {
    uint32_t s = (uint32_t)__cvta_generic_to_shared(smem);
    int sz = pred ? 16 : 0;
    asm volatile("cp.async.cg.shared.global [%0], [%1], 16, %2;"
                 :: "r"(s), "l"(gmem), "r"(sz));
}

__device__ __forceinline__ uint32_t f2tf32(float f) {
    uint32_t r;
    asm("cvt.rna.tf32.f32 %0, %1;" : "=r"(r) : "f"(f));
    return r;
}

#define LDA 20   // 16 used + 4 pad: conflict-free fragment loads

__global__ __launch_bounds__(256, 2)
void gemm_tc_kernel(const float* __restrict__ Aagg,
                    const float* __restrict__ Aself,
                    const float* __restrict__ Wl, const float* __restrict__ Wr,
                    const float* __restrict__ bias,
                    float* __restrict__ out, int M) {
    __shared__ float As[2][128][LDA];
    __shared__ float Bs[2][128][LDA];

    const int bm = blockIdx.y * 128;
    const int bn = blockIdx.x * 128;
    const int t = threadIdx.x;
    const int wid = t >> 5;
    const int lane = t & 31;
    const int wm = wid & 3;
    const int wn = wid >> 2;
    const int gid = lane >> 2;
    const int tig = lane & 3;

    float acc[2][8][4];
#pragma unroll
    for (int mi = 0; mi < 2; mi++)
#pragma unroll
        for (int ni = 0; ni < 8; ni++)
#pragma unroll
            for (int j = 0; j < 4; j++) acc[mi][ni][j] = 0.0f;

    auto load_tile = [&](int stage, int kt) {
        const int phase = kt >> 4;
        const int kloc = (kt & 15) << 4;
        const float* Ap = phase ? Aself : Aagg;
        const float* Bp = phase ? Wr : Wl;
#pragma unroll
        for (int i = 0; i < 2; i++) {
            int c = t + i * 256;
            int row = c >> 2;
            int seg = c & 3;
            int gr = bm + row;
            cp_async16(&As[stage][row][seg * 4],
                       Ap + (size_t)gr * DIM + kloc + seg * 4, gr < M);
            cp_async16(&Bs[stage][row][seg * 4],
                       Bp + (size_t)(bn + row) * DIM + kloc + seg * 4, true);
        }
        asm volatile("cp.async.commit_group;" ::: "memory");
    };

    load_tile(0, 0);

#pragma unroll 1
    for (int kt = 0; kt < 32; kt++) {
        const int s = kt & 1;
        if (kt + 1 < 32) {
            load_tile(1 - s, kt + 1);
            asm volatile("cp.async.wait_group 1;" ::: "memory");
        } else {
            asm volatile("cp.async.wait_group 0;" ::: "memory");
        }
        __syncthreads();

#pragma unroll
        for (int kk = 0; kk < 2; kk++) {
            const int c0 = kk * 8 + tig;
            uint32_t aR[2][4];
#pragma unroll
            for (int mi = 0; mi < 2; mi++) {
                int r0 = wm * 32 + mi * 16 + gid;
                aR[mi][0] = f2tf32(As[s][r0][c0]);
                aR[mi][1] = f2tf32(As[s][r0 + 8][c0]);
                aR[mi][2] = f2tf32(As[s][r0][c0 + 4]);
                aR[mi][3] = f2tf32(As[s][r0 + 8][c0 + 4]);
            }
            uint32_t bR[8][2];
#pragma unroll
            for (int ni = 0; ni < 8; ni++) {
                int n0 = wn * 64 + ni * 8 + gid;
                bR[ni][0] = f2tf32(Bs[s][n0][c0]);
                bR[ni][1] = f2tf32(Bs[s][n0][c0 + 4]);
            }
#pragma unroll
            for (int mi = 0; mi < 2; mi++)
#pragma unroll
                for (int ni = 0; ni < 8; ni++) {
                    asm volatile(
                        "mma.sync.aligned.m16n8k8.row.col.f32.tf32.tf32.f32 "
                        "{%0,%1,%2,%3}, {%4,%5,%6,%7}, {%8,%9}, {%0,%1,%2,%3};"
                        : "+f"(acc[mi][ni][0]), "+f"(acc[mi][ni][1]),
                          "+f"(acc[mi][ni][2]), "+f"(acc[mi][ni][3])
                        : "r"(aR[mi][0]), "r"(aR[mi][1]), "r"(aR[mi][2]), "r"(aR[mi][3]),
                          "r"(bR[ni][0]), "r"(bR[ni][1]));
                }
        }
        __syncthreads();
    }

#pragma unroll
    for (int ni = 0; ni < 8; ni++) {
        int col = bn + wn * 64 + ni * 8 + 2 * tig;
        float bx = bias[col], by = bias[col + 1];
#pragma unroll
        for (int mi = 0; mi < 2; mi++) {
            int r0 = bm + wm * 32 + mi * 16 + gid;
            if (r0 < M) {
                float2 o = make_float2(acc[mi][ni][0] + bx, acc[mi][ni][1] + by);
                *reinterpret_cast<float2*>(out + (size_t)r0 * DIM + col) = o;
            }
            if (r0 + 8 < M) {
                float2 o = make_float2(acc[mi][ni][2] + bx, acc[mi][ni][3] + by);
                *reinterpret_cast<float2*>(out + (size_t)(r0 + 8) * DIM + col) = o;
            }
        }
    }
}

// ---------------- L2 normalize + ReLU (both matrices, grid.y=2) ----------------
__global__ void norm_relu2_kernel(float* __restrict__ xP, float* __restrict__ xA, int n) {
    int row = blockIdx.x * (blockDim.x >> 5) + (threadIdx.x >> 5);
    if (row >= n) return;
    float* x = blockIdx.y ? xA : xP;
    int lane = threadIdx.x & 31;
    float4* p = reinterpret_cast<float4*>(x + (size_t)row * DIM);
    float4 v0 = p[lane];
    float4 v1 = p[lane + 32];
    float s = v0.x * v0.x + v0.y * v0.y + v0.z * v0.z + v0.w * v0.w
            + v1.x * v1.x + v1.y * v1.y + v1.z * v1.z + v1.w * v1.w;
#pragma unroll
    for (int o = 16; o; o >>= 1) s += __shfl_xor_sync(0xFFFFFFFFu, s, o);
    float inv = 1.0f / fmaxf(sqrtf(s), 1e-12f);
    v0.x = fmaxf(v0.x * inv, 0.f); v0.y = fmaxf(v0.y * inv, 0.f);
    v0.z = fmaxf(v0.z * inv, 0.f); v0.w = fmaxf(v0.w * inv, 0.f);
    v1.x = fmaxf(v1.x * inv, 0.f); v1.y = fmaxf(v1.y * inv, 0.f);
    v1.z = fmaxf(v1.z * inv, 0.f); v1.w = fmaxf(v1.w * inv, 0.f);
    p[lane] = v0;
    p[lane + 32] = v1;
}

// ---------------- host orchestration ----------------
extern "C" void kernel_launch(void* const* d_in, const int* in_sizes, int n_in,
                              void* d_out, int out_size) {
    (void)in_sizes; (void)n_in; (void)out_size;
    const float* xa_in = (const float*)d_in[0];
    const float* xp_in = (const float*)d_in[1];
    const float* Wl    = (const float*)d_in[2];
    const float* bl    = (const float*)d_in[3];
    const float* Wr    = (const float*)d_in[4];
    const int*   e_ap  = (const int*)d_in[5];
    const int*   e_pa  = (const int*)d_in[6];
    float* out = (float*)d_out;

    float *bufA[2], *bufP[2], *aggA, *aggP;
    int *degA, *degP, *offA, *offP, *curA, *curP, *csrA, *csrP;
    cudaGetSymbolAddress((void**)&bufA[0], g_bufA0);
    cudaGetSymbolAddress((void**)&bufA[1], g_bufA1);
    cudaGetSymbolAddress((void**)&bufP[0], g_bufP0);
    cudaGetSymbolAddress((void**)&bufP[1], g_bufP1);
    cudaGetSymbolAddress((void**)&aggA, g_aggA);
    cudaGetSymbolAddress((void**)&aggP, g_aggP);
    cudaGetSymbolAddress((void**)&degA, g_degA);
    cudaGetSymbolAddress((void**)&degP, g_degP);
    cudaGetSymbolAddress((void**)&offA, g_offA);
    cudaGetSymbolAddress((void**)&offP, g_offP);
    cudaGetSymbolAddress((void**)&curA, g_curA);
    cudaGetSymbolAddress((void**)&curP, g_curP);
    cudaGetSymbolAddress((void**)&csrA, g_csrA);
    cudaGetSymbolAddress((void**)&csrP, g_csrP);

    // ---- CSR build (once per launch) ----
    cudaMemsetAsync(degA, 0, N_NODES * sizeof(int));
    cudaMemsetAsync(degP, 0, N_NODES * sizeof(int));
    {
        dim3 g((N_EDGES + 255) / 256, 2);
        deg2_kernel<<<g, 256>>>(e_ap + N_EDGES, degP, e_pa + N_EDGES, degA, N_EDGES);
    }
    scan2_kernel<<<2, 1024>>>(degP, offP, degA, offA, N_NODES);
    cudaMemcpyAsync(curP, offP, N_NODES * sizeof(int), cudaMemcpyDeviceToDevice);
    cudaMemcpyAsync(curA, offA, N_NODES * sizeof(int), cudaMemcpyDeviceToDevice);
    {
        dim3 g((N_EDGES + 255) / 256, 2);
        fill2_kernel<<<g, 256>>>(e_ap, curP, csrP, e_pa, curA, csrA, N_EDGES);
    }

    const float* inA = xa_in;
    const float* inP = xp_in;

    dim3 gGrid(DIM / 128, (N_NODES + 127) / 128);   // (2, 391)
    dim3 wGrid((N_NODES + 7) / 8, 2);               // warp-per-row kernels, both dirs

    for (int l = 0; l < N_LAYERS; l++) {
        const bool last = (l == N_LAYERS - 1);
        float* outA = last ? out : bufA[l & 1];
        float* outP = last ? out + (size_t)N_NODES * DIM : bufP[l & 1];

        gather2_kernel<<<wGrid, 256>>>(inA, offP, csrP, aggP,
                                       inP, offA, csrA, aggA, N_NODES);

        const float* Wl_p = Wl + ((size_t)l * 2 + 0) * DIM * DIM;
        const float* Wr_p = Wr + ((size_t)l * 2 + 0) * DIM * DIM;
        const float* bl_p = bl + ((size_t)l * 2 + 0) * DIM;
        const float* Wl_a = Wl + ((size_t)l * 2 + 1) * DIM * DIM;
        const float* Wr_a = Wr + ((size_t)l * 2 + 1) * DIM * DIM;
        const float* bl_a = bl + ((size_t)l * 2 + 1) * DIM;

        gemm_tc_kernel<<<gGrid, 256>>>(aggP, inP, Wl_p, Wr_p, bl_p, outP, N_NODES);
        gemm_tc_kernel<<<gGrid, 256>>>(aggA, inA, Wl_a, Wr_a, bl_a, outA, N_NODES);

        if (!last)
            norm_relu2_kernel<<<wGrid, 256>>>(outP, outA, N_NODES);

        inA = outA;
        inP = outP;
    }
}

// round 6
// speedup vs baseline: 1.2184x; 1.0774x over previous
#include <cuda_runtime.h>
#include <cstdint>
#include <cstddef>

#define N_NODES 50000
#define DIM 256
#define N_EDGES 800000
#define N_LAYERS 5
#define W_ELEMS (N_LAYERS * 2 * DIM * DIM)   // 655360 per tensor

// ---------------- device scratch (allocation-free: .bss globals) ----------------
__device__ float g_bufA0[N_NODES * DIM];
__device__ float g_bufA1[N_NODES * DIM];
__device__ float g_bufP0[N_NODES * DIM];
__device__ float g_bufP1[N_NODES * DIM];
__device__ float g_aggA[N_NODES * DIM];
__device__ float g_aggP[N_NODES * DIM];
__device__ int   g_degA[N_NODES];
__device__ int   g_degP[N_NODES];
__device__ int   g_offA[N_NODES + 1];
__device__ int   g_offP[N_NODES + 1];
__device__ int   g_curA[N_NODES];
__device__ int   g_curP[N_NODES];
__device__ int   g_csrA[N_EDGES];
__device__ int   g_csrP[N_EDGES];
__device__ float g_rWl[W_ELEMS];   // tf32-pre-rounded weights
__device__ float g_rWr[W_ELEMS];

// ---------------- CSR build: degree count (both directions, grid.y=2) ----------------
__global__ void deg2_kernel(const int* __restrict__ dstP, int* __restrict__ degP,
                            const int* __restrict__ dstA, int* __restrict__ degA, int E) {
    int e = blockIdx.x * blockDim.x + threadIdx.x;
    if (e < E) {
        if (blockIdx.y == 0) atomicAdd(&degP[dstP[e]], 1);
        else                 atomicAdd(&degA[dstA[e]], 1);
    }
}

// ---------------- CSR build: coarsened scan, one block per direction ----------------
__global__ void scan2_kernel(const int* __restrict__ d0, int* __restrict__ o0,
                             const int* __restrict__ d1, int* __restrict__ o1, int n) {
    const int* deg = blockIdx.x ? d1 : d0;
    int*       off = blockIdx.x ? o1 : o0;
    const int tid = threadIdx.x;
    const int nthr = blockDim.x;                 // 1024
    const int chunk = (n + nthr - 1) / nthr;
    const int s = tid * chunk;
    const int e = min(s + chunk, n);

    int sum = 0;
    for (int i = s; i < e; i++) sum += deg[i];

    __shared__ int wsum[32];
    int x = sum;
    const int lane = tid & 31, wid = tid >> 5;
#pragma unroll
    for (int o = 1; o < 32; o <<= 1) {
        int y = __shfl_up_sync(0xFFFFFFFFu, x, o);
        if (lane >= o) x += y;
    }
    if (lane == 31) wsum[wid] = x;
    __syncthreads();
    if (tid < 32) {
        int w = wsum[tid];
#pragma unroll
        for (int o = 1; o < 32; o <<= 1) {
            int y = __shfl_up_sync(0xFFFFFFFFu, w, o);
            if (tid >= o) w += y;
        }
        wsum[tid] = w;
    }
    __syncthreads();
    int run = x - sum + (wid ? wsum[wid - 1] : 0);
    for (int i = s; i < e; i++) { int v = deg[i]; off[i] = run; run += v; }
    if (tid == 0) off[n] = wsum[31];
}

// ---------------- CSR build: slot fill (both directions, grid.y=2) ----------------
__global__ void fill2_kernel(const int* __restrict__ eap, int* __restrict__ curP, int* __restrict__ csrP,
                             const int* __restrict__ epa, int* __restrict__ curA, int* __restrict__ csrA,
                             int E) {
    int e = blockIdx.x * blockDim.x + threadIdx.x;
    if (e < E) {
        if (blockIdx.y == 0) {
            int slot = atomicAdd(&curP[eap[E + e]], 1);
            csrP[slot] = eap[e];
        } else {
            int slot = atomicAdd(&curA[epa[E + e]], 1);
            csrA[slot] = epa[e];
        }
    }
}

// ---------------- weight pre-rounding: f32 -> tf32(rna) bits, once per launch ----------------
__global__ void round_w_kernel(const float* __restrict__ wl, const float* __restrict__ wr,
                               float* __restrict__ rwl, float* __restrict__ rwr, int n4) {
    int i = blockIdx.x * blockDim.x + threadIdx.x;
    if (i < n4) {
        float4 a = reinterpret_cast<const float4*>(wl)[i];
        float4 b = reinterpret_cast<const float4*>(wr)[i];
        uint4 ra, rb;
        asm("cvt.rna.tf32.f32 %0, %1;" : "=r"(ra.x) : "f"(a.x));
        asm("cvt.rna.tf32.f32 %0, %1;" : "=r"(ra.y) : "f"(a.y));
        asm("cvt.rna.tf32.f32 %0, %1;" : "=r"(ra.z) : "f"(a.z));
        asm("cvt.rna.tf32.f32 %0, %1;" : "=r"(ra.w) : "f"(a.w));
        asm("cvt.rna.tf32.f32 %0, %1;" : "=r"(rb.x) : "f"(b.x));
        asm("cvt.rna.tf32.f32 %0, %1;" : "=r"(rb.y) : "f"(b.y));
        asm("cvt.rna.tf32.f32 %0, %1;" : "=r"(rb.z) : "f"(b.z));
        asm("cvt.rna.tf32.f32 %0, %1;" : "=r"(rb.w) : "f"(b.w));
        reinterpret_cast<uint4*>(rwl)[i] = ra;
        reinterpret_cast<uint4*>(rwr)[i] = rb;
    }
}

// ---------------- gather (both directions in one launch via grid.y) ----------------
__global__ void gather2_kernel(const float* __restrict__ xA, const int* __restrict__ offP,
                               const int* __restrict__ csrP, float* __restrict__ aggP,
                               const float* __restrict__ xP, const int* __restrict__ offA,
                               const int* __restrict__ csrA, float* __restrict__ aggA,
                               int n) {
    int row = blockIdx.x * (blockDim.x >> 5) + (threadIdx.x >> 5);
    if (row >= n) return;
    const int lane = threadIdx.x & 31;
    const float* x;
    const int *off, *csr;
    float* agg;
    if (blockIdx.y == 0) { x = xA; off = offP; csr = csrP; agg = aggP; }
    else                 { x = xP; off = offA; csr = csrA; agg = aggA; }
    const int beg = off[row], end = off[row + 1];

    float4 s0 = make_float4(0.f, 0.f, 0.f, 0.f);
    float4 s1 = make_float4(0.f, 0.f, 0.f, 0.f);
    int e = beg;
    for (; e + 1 < end; e += 2) {
        int i0 = csr[e], i1 = csr[e + 1];
        const float4* p0 = reinterpret_cast<const float4*>(x + (size_t)i0 * DIM);
        const float4* p1 = reinterpret_cast<const float4*>(x + (size_t)i1 * DIM);
        float4 a = p0[lane], b = p0[lane + 32];
        float4 c = p1[lane], d = p1[lane + 32];
        s0.x += a.x; s0.y += a.y; s0.z += a.z; s0.w += a.w;
        s1.x += b.x; s1.y += b.y; s1.z += b.z; s1.w += b.w;
        s0.x += c.x; s0.y += c.y; s0.z += c.z; s0.w += c.w;
        s1.x += d.x; s1.y += d.y; s1.z += d.z; s1.w += d.w;
    }
    if (e < end) {
        const float4* p0 = reinterpret_cast<const float4*>(x + (size_t)csr[e] * DIM);
        float4 a = p0[lane], b = p0[lane + 32];
        s0.x += a.x; s0.y += a.y; s0.z += a.z; s0.w += a.w;
        s1.x += b.x; s1.y += b.y; s1.z += b.z; s1.w += b.w;
    }
    const float inv = 1.0f / fmaxf((float)(end - beg), 1.0f);
    s0.x *= inv; s0.y *= inv; s0.z *= inv; s0.w *= inv;
    s1.x *= inv; s1.y *= inv; s1.z *= inv; s1.w *= inv;
    float4* o = reinterpret_cast<float4*>(agg + (size_t)row * DIM);
    o[lane] = s0;
    o[lane + 32] = s1;
}

// ---------------- tf32 tensor-core fused dual GEMM (both directions, grid.z=2) ----------------
// out = agg @ Wl^T + self @ Wr^T + b. W matrices pre-rounded to tf32 (no in-loop cvt).
// BM=128, BN=128, BK=16, 3-stage cp.async pipeline, 8 warps, warp tile 32x64.

struct GemmArgs {
    const float *agg, *self_, *wl, *wr, *bias;
    float* out;
};

__device__ __forceinline__ void cp_async16(void* smem, const void* gmem, bool pred) {
    uint32_t s = (uint32_t)__cvta_generic_to_shared(smem);
    int sz = pred ? 16 : 0;
    asm volatile("cp.async.cg.shared.global [%0], [%1], 16, %2;"
                 :: "r"(s), "l"(gmem), "r"(sz));
}

__device__ __forceinline__ uint32_t f2tf32(float f) {
    uint32_t r;
    asm("cvt.rna.tf32.f32 %0, %1;" : "=r"(r) : "f"(f));
    return r;
}

#define LDA 20            // 16 used + 4 pad: conflict-free fragment loads
#define STG_F (128 * LDA) // floats per tile per stage

__global__ __launch_bounds__(256, 2)
void gemm_tc_kernel(GemmArgs g0, GemmArgs g1, int M) {
    extern __shared__ float sm[];
    float* As = sm;                 // [3][128][LDA]
    float* Bs = sm + 3 * STG_F;     // [3][128][LDA]

    const GemmArgs* G = blockIdx.z ? &g1 : &g0;
    const float* Aagg = G->agg;
    const float* Aself = G->self_;
    const float* Wl = G->wl;
    const float* Wr = G->wr;

    const int bm = blockIdx.y * 128;
    const int bn = blockIdx.x * 128;
    const int t = threadIdx.x;
    const int wid = t >> 5;
    const int lane = t & 31;
    const int wm = wid & 3;
    const int wn = wid >> 2;
    const int gid = lane >> 2;
    const int tig = lane & 3;

    float acc[2][8][4];
#pragma unroll
    for (int mi = 0; mi < 2; mi++)
#pragma unroll
        for (int ni = 0; ni < 8; ni++)
#pragma unroll
            for (int j = 0; j < 4; j++) acc[mi][ni][j] = 0.0f;

    const int lrow = t >> 2;        // 0..63  (A rows t/4 group? no: see below)
    auto load_tile = [&](int stage, int kt) {
        const int phase = kt >> 4;
        const int kloc = (kt & 15) << 4;
        const float* Ap = phase ? Aself : Aagg;
        const float* Bp = phase ? Wr : Wl;
        float* as = As + stage * STG_F;
        float* bs = Bs + stage * STG_F;
#pragma unroll
        for (int i = 0; i < 2; i++) {
            int c = t + i * 256;    // 0..511
            int row = c >> 2;
            int seg = c & 3;
            int gr = bm + row;
            cp_async16(as + row * LDA + seg * 4,
                       Ap + (size_t)gr * DIM + kloc + seg * 4, gr < M);
            cp_async16(bs + row * LDA + seg * 4,
                       Bp + (size_t)(bn + row) * DIM + kloc + seg * 4, true);
        }
        asm volatile("cp.async.commit_group;" ::: "memory");
    };
    (void)lrow;

    load_tile(0, 0);
    load_tile(1, 1);

#pragma unroll 1
    for (int kt = 0; kt < 32; kt++) {
        const int s = kt % 3;
        asm volatile("cp.async.wait_group 1;" ::: "memory");
        __syncthreads();
        if (kt + 2 < 32) load_tile((kt + 2) % 3, kt + 2);

        const float* as = As + s * STG_F;
        const uint32_t* bs = reinterpret_cast<const uint32_t*>(Bs + s * STG_F);

#pragma unroll
        for (int kk = 0; kk < 2; kk++) {
            const int c0 = kk * 8 + tig;
            uint32_t aR[2][4];
#pragma unroll
            for (int mi = 0; mi < 2; mi++) {
                int r0 = wm * 32 + mi * 16 + gid;
                aR[mi][0] = f2tf32(as[r0 * LDA + c0]);
                aR[mi][1] = f2tf32(as[(r0 + 8) * LDA + c0]);
                aR[mi][2] = f2tf32(as[r0 * LDA + c0 + 4]);
                aR[mi][3] = f2tf32(as[(r0 + 8) * LDA + c0 + 4]);
            }
            uint32_t bR[8][2];
#pragma unroll
            for (int ni = 0; ni < 8; ni++) {
                int n0 = wn * 64 + ni * 8 + gid;
                bR[ni][0] = bs[n0 * LDA + c0];        // pre-rounded tf32 bits
                bR[ni][1] = bs[n0 * LDA + c0 + 4];
            }
#pragma unroll
            for (int mi = 0; mi < 2; mi++)
#pragma unroll
                for (int ni = 0; ni < 8; ni++) {
                    asm volatile(
                        "mma.sync.aligned.m16n8k8.row.col.f32.tf32.tf32.f32 "
                        "{%0,%1,%2,%3}, {%4,%5,%6,%7}, {%8,%9}, {%0,%1,%2,%3};"
                        : "+f"(acc[mi][ni][0]), "+f"(acc[mi][ni][1]),
                          "+f"(acc[mi][ni][2]), "+f"(acc[mi][ni][3])
                        : "r"(aR[mi][0]), "r"(aR[mi][1]), "r"(aR[mi][2]), "r"(aR[mi][3]),
                          "r"(bR[ni][0]), "r"(bR[ni][1]));
                }
        }
    }

    const float* bias = G->bias;
    float* out = G->out;
#pragma unroll
    for (int ni = 0; ni < 8; ni++) {
        int col = bn + wn * 64 + ni * 8 + 2 * tig;
        float bx = bias[col], by = bias[col + 1];
#pragma unroll
        for (int mi = 0; mi < 2; mi++) {
            int r0 = bm + wm * 32 + mi * 16 + gid;
            if (r0 < M) {
                float2 o = make_float2(acc[mi][ni][0] + bx, acc[mi][ni][1] + by);
                *reinterpret_cast<float2*>(out + (size_t)r0 * DIM + col) = o;
            }
            if (r0 + 8 < M) {
                float2 o = make_float2(acc[mi][ni][2] + bx, acc[mi][ni][3] + by);
                *reinterpret_cast<float2*>(out + (size_t)(r0 + 8) * DIM + col) = o;
            }
        }
    }
}

// ---------------- L2 normalize + ReLU (both matrices, grid.y=2) ----------------
__global__ void norm_relu2_kernel(float* __restrict__ xP, float* __restrict__ xA, int n) {
    int row = blockIdx.x * (blockDim.x >> 5) + (threadIdx.x >> 5);
    if (row >= n) return;
    float* x = blockIdx.y ? xA : xP;
    int lane = threadIdx.x & 31;
    float4* p = reinterpret_cast<float4*>(x + (size_t)row * DIM);
    float4 v0 = p[lane];
    float4 v1 = p[lane + 32];
    float s = v0.x * v0.x + v0.y * v0.y + v0.z * v0.z + v0.w * v0.w
            + v1.x * v1.x + v1.y * v1.y + v1.z * v1.z + v1.w * v1.w;
#pragma unroll
    for (int o = 16; o; o >>= 1) s += __shfl_xor_sync(0xFFFFFFFFu, s, o);
    float inv = 1.0f / fmaxf(sqrtf(s), 1e-12f);
    v0.x = fmaxf(v0.x * inv, 0.f); v0.y = fmaxf(v0.y * inv, 0.f);
    v0.z = fmaxf(v0.z * inv, 0.f); v0.w = fmaxf(v0.w * inv, 0.f);
    v1.x = fmaxf(v1.x * inv, 0.f); v1.y = fmaxf(v1.y * inv, 0.f);
    v1.z = fmaxf(v1.z * inv, 0.f); v1.w = fmaxf(v1.w * inv, 0.f);
    p[lane] = v0;
    p[lane + 32] = v1;
}

// ---------------- host orchestration ----------------
extern "C" void kernel_launch(void* const* d_in, const int* in_sizes, int n_in,
                              void* d_out, int out_size) {
    (void)in_sizes; (void)n_in; (void)out_size;
    const float* xa_in = (const float*)d_in[0];
    const float* xp_in = (const float*)d_in[1];
    const float* Wl    = (const float*)d_in[2];
    const float* bl    = (const float*)d_in[3];
    const float* Wr    = (const float*)d_in[4];
    const int*   e_ap  = (const int*)d_in[5];
    const int*   e_pa  = (const int*)d_in[6];
    float* out = (float*)d_out;

    float *bufA[2], *bufP[2], *aggA, *aggP, *rWl, *rWr;
    int *degA, *degP, *offA, *offP, *curA, *curP, *csrA, *csrP;
    cudaGetSymbolAddress((void**)&bufA[0], g_bufA0);
    cudaGetSymbolAddress((void**)&bufA[1], g_bufA1);
    cudaGetSymbolAddress((void**)&bufP[0], g_bufP0);
    cudaGetSymbolAddress((void**)&bufP[1], g_bufP1);
    cudaGetSymbolAddress((void**)&aggA, g_aggA);
    cudaGetSymbolAddress((void**)&aggP, g_aggP);
    cudaGetSymbolAddress((void**)&rWl, g_rWl);
    cudaGetSymbolAddress((void**)&rWr, g_rWr);
    cudaGetSymbolAddress((void**)&degA, g_degA);
    cudaGetSymbolAddress((void**)&degP, g_degP);
    cudaGetSymbolAddress((void**)&offA, g_offA);
    cudaGetSymbolAddress((void**)&offP, g_offP);
    cudaGetSymbolAddress((void**)&curA, g_curA);
    cudaGetSymbolAddress((void**)&curP, g_curP);
    cudaGetSymbolAddress((void**)&csrA, g_csrA);
    cudaGetSymbolAddress((void**)&csrP, g_csrP);

    // allow 60KB dynamic smem for the 3-stage GEMM (immediate, idempotent, not a stream op)
    static bool attr_set = false;
    if (!attr_set) {
        cudaFuncSetAttribute(gemm_tc_kernel, cudaFuncAttributeMaxDynamicSharedMemorySize,
                             6 * STG_F * (int)sizeof(float));
        attr_set = true;
    }

    // ---- weight pre-rounding + CSR build (once per launch) ----
    round_w_kernel<<<(W_ELEMS / 4 + 255) / 256, 256>>>(Wl, Wr, rWl, rWr, W_ELEMS / 4);
    cudaMemsetAsync(degA, 0, N_NODES * sizeof(int));
    cudaMemsetAsync(degP, 0, N_NODES * sizeof(int));
    {
        dim3 g((N_EDGES + 255) / 256, 2);
        deg2_kernel<<<g, 256>>>(e_ap + N_EDGES, degP, e_pa + N_EDGES, degA, N_EDGES);
    }
    scan2_kernel<<<2, 1024>>>(degP, offP, degA, offA, N_NODES);
    cudaMemcpyAsync(curP, offP, N_NODES * sizeof(int), cudaMemcpyDeviceToDevice);
    cudaMemcpyAsync(curA, offA, N_NODES * sizeof(int), cudaMemcpyDeviceToDevice);
    {
        dim3 g((N_EDGES + 255) / 256, 2);
        fill2_kernel<<<g, 256>>>(e_ap, curP, csrP, e_pa, curA, csrA, N_EDGES);
    }

    const float* inA = xa_in;
    const float* inP = xp_in;

    dim3 gGrid(DIM / 128, (N_NODES + 127) / 128, 2);   // (2, 391, 2)
    dim3 wGrid((N_NODES + 7) / 8, 2);
    const int smemBytes = 6 * STG_F * (int)sizeof(float);

    for (int l = 0; l < N_LAYERS; l++) {
        const bool last = (l == N_LAYERS - 1);
        float* outA = last ? out : bufA[l & 1];
        float* outP = last ? out + (size_t)N_NODES * DIM : bufP[l & 1];

        gather2_kernel<<<wGrid, 256>>>(inA, offP, csrP, aggP,
                                       inP, offA, csrA, aggA, N_NODES);

        GemmArgs gp, ga;
        gp.agg = aggP; gp.self_ = inP;
        gp.wl = rWl + ((size_t)l * 2 + 0) * DIM * DIM;
        gp.wr = rWr + ((size_t)l * 2 + 0) * DIM * DIM;
        gp.bias = bl + ((size_t)l * 2 + 0) * DIM;
        gp.out = outP;
        ga.agg = aggA; ga.self_ = inA;
        ga.wl = rWl + ((size_t)l * 2 + 1) * DIM * DIM;
        ga.wr = rWr + ((size_t)l * 2 + 1) * DIM * DIM;
        ga.bias = bl + ((size_t)l * 2 + 1) * DIM;
        ga.out = outA;

        gemm_tc_kernel<<<gGrid, 256, smemBytes>>>(gp, ga, N_NODES);

        if (!last)
            norm_relu2_kernel<<<wGrid, 256>>>(outP, outA, N_NODES);

        inA = outA;
        inP = outP;
    }
}

// round 7
// speedup vs baseline: 2.1025x; 1.7257x over previous
#include <cuda_runtime.h>
#include <cuda_fp16.h>
#include <cstdint>
#include <cstddef>

#define N_NODES 50000
#define DIM 256
#define N_EDGES 800000
#define N_LAYERS 5
#define W_ELEMS (N_LAYERS * 2 * DIM * DIM)   // 655360 per tensor

// ---------------- device scratch (allocation-free: .bss globals) ----------------
__device__ __half g_xa16[N_NODES * DIM];
__device__ __half g_xp16[N_NODES * DIM];
__device__ __half g_bufA0[N_NODES * DIM];
__device__ __half g_bufA1[N_NODES * DIM];
__device__ __half g_bufP0[N_NODES * DIM];
__device__ __half g_bufP1[N_NODES * DIM];
__device__ __half g_aggA[N_NODES * DIM];
__device__ __half g_aggP[N_NODES * DIM];
__device__ __half g_hWl[W_ELEMS];
__device__ __half g_hWr[W_ELEMS];
__device__ int    g_degA[N_NODES];
__device__ int    g_degP[N_NODES];
__device__ int    g_offA[N_NODES + 1];
__device__ int    g_offP[N_NODES + 1];
__device__ int    g_curA[N_NODES];
__device__ int    g_curP[N_NODES];
__device__ int    g_csrA[N_EDGES];
__device__ int    g_csrP[N_EDGES];

// ---------------- fp32 -> fp16 convert (two tensors per launch) ----------------
__global__ void cvt2h_kernel(const float* __restrict__ a, const float* __restrict__ b,
                             __half* __restrict__ ah, __half* __restrict__ bh, int n4) {
    int i = blockIdx.x * blockDim.x + threadIdx.x;
    if (i < n4) {
        float4 va = reinterpret_cast<const float4*>(a)[i];
        float4 vb = reinterpret_cast<const float4*>(b)[i];
        __half2 ha0 = __floats2half2_rn(va.x, va.y);
        __half2 ha1 = __floats2half2_rn(va.z, va.w);
        __half2 hb0 = __floats2half2_rn(vb.x, vb.y);
        __half2 hb1 = __floats2half2_rn(vb.z, vb.w);
        reinterpret_cast<__half2*>(ah)[i * 2]     = ha0;
        reinterpret_cast<__half2*>(ah)[i * 2 + 1] = ha1;
        reinterpret_cast<__half2*>(bh)[i * 2]     = hb0;
        reinterpret_cast<__half2*>(bh)[i * 2 + 1] = hb1;
    }
}

// ---------------- CSR build: degree count (both directions, grid.y=2) ----------------
__global__ void deg2_kernel(const int* __restrict__ dstP, int* __restrict__ degP,
                            const int* __restrict__ dstA, int* __restrict__ degA, int E) {
    int e = blockIdx.x * blockDim.x + threadIdx.x;
    if (e < E) {
        if (blockIdx.y == 0) atomicAdd(&degP[dstP[e]], 1);
        else                 atomicAdd(&degA[dstA[e]], 1);
    }
}

// ---------------- CSR build: coarsened scan, one block per direction ----------------
__global__ void scan2_kernel(const int* __restrict__ d0, int* __restrict__ o0,
                             const int* __restrict__ d1, int* __restrict__ o1, int n) {
    const int* deg = blockIdx.x ? d1 : d0;
    int*       off = blockIdx.x ? o1 : o0;
    const int tid = threadIdx.x;
    const int nthr = blockDim.x;                 // 1024
    const int chunk = (n + nthr - 1) / nthr;
    const int s = tid * chunk;
    const int e = min(s + chunk, n);

    int sum = 0;
    for (int i = s; i < e; i++) sum += deg[i];

    __shared__ int wsum[32];
    int x = sum;
    const int lane = tid & 31, wid = tid >> 5;
#pragma unroll
    for (int o = 1; o < 32; o <<= 1) {
        int y = __shfl_up_sync(0xFFFFFFFFu, x, o);
        if (lane >= o) x += y;
    }
    if (lane == 31) wsum[wid] = x;
    __syncthreads();
    if (tid < 32) {
        int w = wsum[tid];
#pragma unroll
        for (int o = 1; o < 32; o <<= 1) {
            int y = __shfl_up_sync(0xFFFFFFFFu, w, o);
            if (tid >= o) w += y;
        }
        wsum[tid] = w;
    }
    __syncthreads();
    int run = x - sum + (wid ? wsum[wid - 1] : 0);
    for (int i = s; i < e; i++) { int v = deg[i]; off[i] = run; run += v; }
    if (tid == 0) off[n] = wsum[31];
}

// ---------------- CSR build: slot fill (both directions, grid.y=2) ----------------
__global__ void fill2_kernel(const int* __restrict__ eap, int* __restrict__ curP, int* __restrict__ csrP,
                             const int* __restrict__ epa, int* __restrict__ curA, int* __restrict__ csrA,
                             int E) {
    int e = blockIdx.x * blockDim.x + threadIdx.x;
    if (e < E) {
        if (blockIdx.y == 0) {
            int slot = atomicAdd(&curP[eap[E + e]], 1);
            csrP[slot] = eap[e];
        } else {
            int slot = atomicAdd(&curA[epa[E + e]], 1);
            csrA[slot] = epa[e];
        }
    }
}

// ---------------- gather (fp16 rows; both directions in one launch via grid.y) ----------------
// agg[dst] = mean over neighbors of x[src]; warp per row, one uint4 (8 halfs) per lane.
__global__ void gather2_kernel(const __half* __restrict__ xA, const int* __restrict__ offP,
                               const int* __restrict__ csrP, __half* __restrict__ aggP,
                               const __half* __restrict__ xP, const int* __restrict__ offA,
                               const int* __restrict__ csrA, __half* __restrict__ aggA,
                               int n) {
    int row = blockIdx.x * (blockDim.x >> 5) + (threadIdx.x >> 5);
    if (row >= n) return;
    const int lane = threadIdx.x & 31;
    const __half* x;
    const int *off, *csr;
    __half* agg;
    if (blockIdx.y == 0) { x = xA; off = offP; csr = csrP; agg = aggP; }
    else                 { x = xP; off = offA; csr = csrA; agg = aggA; }
    const int beg = off[row], end = off[row + 1];

    float s[8] = {0.f, 0.f, 0.f, 0.f, 0.f, 0.f, 0.f, 0.f};
    int e = beg;
    for (; e + 1 < end; e += 2) {
        int i0 = csr[e], i1 = csr[e + 1];
        uint4 v0 = reinterpret_cast<const uint4*>(x + (size_t)i0 * DIM)[lane];
        uint4 v1 = reinterpret_cast<const uint4*>(x + (size_t)i1 * DIM)[lane];
        const __half2* h0 = reinterpret_cast<const __half2*>(&v0);
        const __half2* h1 = reinterpret_cast<const __half2*>(&v1);
#pragma unroll
        for (int j = 0; j < 4; j++) {
            float2 f0 = __half22float2(h0[j]);
            float2 f1 = __half22float2(h1[j]);
            s[j * 2]     += f0.x + f1.x;
            s[j * 2 + 1] += f0.y + f1.y;
        }
    }
    if (e < end) {
        uint4 v0 = reinterpret_cast<const uint4*>(x + (size_t)csr[e] * DIM)[lane];
        const __half2* h0 = reinterpret_cast<const __half2*>(&v0);
#pragma unroll
        for (int j = 0; j < 4; j++) {
            float2 f0 = __half22float2(h0[j]);
            s[j * 2]     += f0.x;
            s[j * 2 + 1] += f0.y;
        }
    }
    const float inv = 1.0f / fmaxf((float)(end - beg), 1.0f);
    uint4 o;
    __half2* ho = reinterpret_cast<__half2*>(&o);
#pragma unroll
    for (int j = 0; j < 4; j++)
        ho[j] = __floats2half2_rn(s[j * 2] * inv, s[j * 2 + 1] * inv);
    reinterpret_cast<uint4*>(agg + (size_t)row * DIM)[lane] = o;
}

// ---------------- fp16 tensor-core fused dual GEMM (both directions, grid.z=2) ----------------
// out = agg @ Wl^T + self @ Wr^T + b (fp32 accum). m16n8k16, BM=128, BN=128, BK=32,
// 3-stage cp.async, XOR-swizzled smem (no padding), 8 warps, warp tile 32x64.

struct GemmArgs {
    const __half *agg, *self_, *wl, *wr;
    const float* bias;
    float* outF;    // non-null on last layer
    __half* outH;   // non-null on hidden layers
};

__device__ __forceinline__ void cp_async16(void* smem, const void* gmem, bool pred) {
    uint32_t s = (uint32_t)__cvta_generic_to_shared(smem);
    int sz = pred ? 16 : 0;
    asm volatile("cp.async.cg.shared.global [%0], [%1], 16, %2;"
                 :: "r"(s), "l"(gmem), "r"(sz));
}

#define STG_H (128 * 32)   // halfs per tile per stage (8KB)

__global__ __launch_bounds__(256, 2)
void gemm_tc_kernel(GemmArgs g0, GemmArgs g1, int M) {
    extern __shared__ __half sm[];
    __half* As = sm;                 // [3][128][32] XOR-swizzled
    __half* Bs = sm + 3 * STG_H;

    const GemmArgs* G = blockIdx.z ? &g1 : &g0;
    const __half* Aagg = G->agg;
    const __half* Aself = G->self_;
    const __half* Wl = G->wl;
    const __half* Wr = G->wr;

    const int bm = blockIdx.y * 128;
    const int bn = blockIdx.x * 128;
    const int t = threadIdx.x;
    const int wid = t >> 5;
    const int lane = t & 31;
    const int wm = wid & 3;
    const int wn = wid >> 2;
    const int gid = lane >> 2;
    const int tig = lane & 3;

    float acc[2][8][4];
#pragma unroll
    for (int mi = 0; mi < 2; mi++)
#pragma unroll
        for (int ni = 0; ni < 8; ni++)
#pragma unroll
            for (int j = 0; j < 4; j++) acc[mi][ni][j] = 0.0f;

    // 16 k-tiles of 32: kt 0..7 phase 0 (agg,Wl), kt 8..15 phase 1 (self,Wr)
    auto load_tile = [&](int stage, int kt) {
        const int phase = kt >> 3;
        const int kloc = (kt & 7) << 5;
        const __half* Ap = phase ? Aself : Aagg;
        const __half* Bp = phase ? Wr : Wl;
        __half* as = As + stage * STG_H;
        __half* bs = Bs + stage * STG_H;
#pragma unroll
        for (int i = 0; i < 2; i++) {
            int c = t + i * 256;          // 0..511
            int row = c >> 2;
            int seg = c & 3;
            int segp = seg ^ ((row >> 1) & 3);
            int gr = bm + row;
            cp_async16(as + row * 32 + segp * 8,
                       Ap + (size_t)gr * DIM + kloc + seg * 8, gr < M);
            cp_async16(bs + row * 32 + segp * 8,
                       Bp + (size_t)(bn + row) * DIM + kloc + seg * 8, true);
        }
        asm volatile("cp.async.commit_group;" ::: "memory");
    };

    load_tile(0, 0);
    load_tile(1, 1);

#pragma unroll 1
    for (int kt = 0; kt < 16; kt++) {
        const int s = kt % 3;
        asm volatile("cp.async.wait_group 1;" ::: "memory");
        __syncthreads();
        if (kt + 2 < 16) load_tile((kt + 2) % 3, kt + 2);

        const uint32_t* asw = reinterpret_cast<const uint32_t*>(As + s * STG_H);
        const uint32_t* bsw = reinterpret_cast<const uint32_t*>(Bs + s * STG_H);

#pragma unroll
        for (int ks = 0; ks < 2; ks++) {      // two m16n8k16 steps within BK=32
            const int gA = ks * 2;            // 4-word group of k-halves [ks*16, ks*16+8)
            uint32_t aR[2][4];
#pragma unroll
            for (int mi = 0; mi < 2; mi++) {
                int r0 = wm * 32 + mi * 16 + gid;
                int r1 = r0 + 8;
                int sw0 = (r0 >> 1) & 3, sw1 = (r1 >> 1) & 3;
                aR[mi][0] = asw[r0 * 16 + ((gA ^ sw0) << 2) + tig];
                aR[mi][1] = asw[r1 * 16 + ((gA ^ sw1) << 2) + tig];
                aR[mi][2] = asw[r0 * 16 + (((gA + 1) ^ sw0) << 2) + tig];
                aR[mi][3] = asw[r1 * 16 + (((gA + 1) ^ sw1) << 2) + tig];
            }
            uint32_t bR[8][2];
#pragma unroll
            for (int ni = 0; ni < 8; ni++) {
                int n0 = wn * 64 + ni * 8 + gid;
                int swn = (n0 >> 1) & 3;
                bR[ni][0] = bsw[n0 * 16 + ((gA ^ swn) << 2) + tig];
                bR[ni][1] = bsw[n0 * 16 + (((gA + 1) ^ swn) << 2) + tig];
            }
#pragma unroll
            for (int mi = 0; mi < 2; mi++)
#pragma unroll
                for (int ni = 0; ni < 8; ni++) {
                    asm volatile(
                        "mma.sync.aligned.m16n8k16.row.col.f32.f16.f16.f32 "
                        "{%0,%1,%2,%3}, {%4,%5,%6,%7}, {%8,%9}, {%0,%1,%2,%3};"
                        : "+f"(acc[mi][ni][0]), "+f"(acc[mi][ni][1]),
                          "+f"(acc[mi][ni][2]), "+f"(acc[mi][ni][3])
                        : "r"(aR[mi][0]), "r"(aR[mi][1]), "r"(aR[mi][2]), "r"(aR[mi][3]),
                          "r"(bR[ni][0]), "r"(bR[ni][1]));
                }
        }
    }

    const float* bias = G->bias;
    float* outF = G->outF;
    __half* outH = G->outH;
#pragma unroll
    for (int ni = 0; ni < 8; ni++) {
        int col = bn + wn * 64 + ni * 8 + 2 * tig;
        float bx = bias[col], by = bias[col + 1];
#pragma unroll
        for (int mi = 0; mi < 2; mi++) {
            int r0 = bm + wm * 32 + mi * 16 + gid;
            float ox0 = acc[mi][ni][0] + bx, oy0 = acc[mi][ni][1] + by;
            float ox1 = acc[mi][ni][2] + bx, oy1 = acc[mi][ni][3] + by;
            if (outH) {
                if (r0 < M)
                    *reinterpret_cast<__half2*>(outH + (size_t)r0 * DIM + col) =
                        __floats2half2_rn(ox0, oy0);
                if (r0 + 8 < M)
                    *reinterpret_cast<__half2*>(outH + (size_t)(r0 + 8) * DIM + col) =
                        __floats2half2_rn(ox1, oy1);
            } else {
                if (r0 < M)
                    *reinterpret_cast<float2*>(outF + (size_t)r0 * DIM + col) =
                        make_float2(ox0, oy0);
                if (r0 + 8 < M)
                    *reinterpret_cast<float2*>(outF + (size_t)(r0 + 8) * DIM + col) =
                        make_float2(ox1, oy1);
            }
        }
    }
}

// ---------------- L2 normalize + ReLU (fp16 rows, both matrices, grid.y=2) ----------------
__global__ void norm_relu2_kernel(__half* __restrict__ xP, __half* __restrict__ xA, int n) {
    int row = blockIdx.x * (blockDim.x >> 5) + (threadIdx.x >> 5);
    if (row >= n) return;
    __half* x = blockIdx.y ? xA : xP;
    int lane = threadIdx.x & 31;
    uint4 v = reinterpret_cast<uint4*>(x + (size_t)row * DIM)[lane];
    __half2* h = reinterpret_cast<__half2*>(&v);
    float f[8];
    float s = 0.f;
#pragma unroll
    for (int j = 0; j < 4; j++) {
        float2 p = __half22float2(h[j]);
        f[j * 2] = p.x; f[j * 2 + 1] = p.y;
        s += p.x * p.x + p.y * p.y;
    }
#pragma unroll
    for (int o = 16; o; o >>= 1) s += __shfl_xor_sync(0xFFFFFFFFu, s, o);
    float inv = 1.0f / fmaxf(sqrtf(s), 1e-12f);
    uint4 ov;
    __half2* ho = reinterpret_cast<__half2*>(&ov);
#pragma unroll
    for (int j = 0; j < 4; j++)
        ho[j] = __floats2half2_rn(fmaxf(f[j * 2] * inv, 0.f), fmaxf(f[j * 2 + 1] * inv, 0.f));
    reinterpret_cast<uint4*>(x + (size_t)row * DIM)[lane] = ov;
}

// ---------------- host orchestration ----------------
extern "C" void kernel_launch(void* const* d_in, const int* in_sizes, int n_in,
                              void* d_out, int out_size) {
    (void)in_sizes; (void)n_in; (void)out_size;
    const float* xa_in = (const float*)d_in[0];
    const float* xp_in = (const float*)d_in[1];
    const float* Wl    = (const float*)d_in[2];
    const float* bl    = (const float*)d_in[3];
    const float* Wr    = (const float*)d_in[4];
    const int*   e_ap  = (const int*)d_in[5];
    const int*   e_pa  = (const int*)d_in[6];
    float* out = (float*)d_out;

    __half *xa16, *xp16, *bufA[2], *bufP[2], *aggA, *aggP, *hWl, *hWr;
    int *degA, *degP, *offA, *offP, *curA, *curP, *csrA, *csrP;
    cudaGetSymbolAddress((void**)&xa16, g_xa16);
    cudaGetSymbolAddress((void**)&xp16, g_xp16);
    cudaGetSymbolAddress((void**)&bufA[0], g_bufA0);
    cudaGetSymbolAddress((void**)&bufA[1], g_bufA1);
    cudaGetSymbolAddress((void**)&bufP[0], g_bufP0);
    cudaGetSymbolAddress((void**)&bufP[1], g_bufP1);
    cudaGetSymbolAddress((void**)&aggA, g_aggA);
    cudaGetSymbolAddress((void**)&aggP, g_aggP);
    cudaGetSymbolAddress((void**)&hWl, g_hWl);
    cudaGetSymbolAddress((void**)&hWr, g_hWr);
    cudaGetSymbolAddress((void**)&degA, g_degA);
    cudaGetSymbolAddress((void**)&degP, g_degP);
    cudaGetSymbolAddress((void**)&offA, g_offA);
    cudaGetSymbolAddress((void**)&offP, g_offP);
    cudaGetSymbolAddress((void**)&curA, g_curA);
    cudaGetSymbolAddress((void**)&curP, g_curP);
    cudaGetSymbolAddress((void**)&csrA, g_csrA);
    cudaGetSymbolAddress((void**)&csrP, g_csrP);

    static bool attr_set = false;
    if (!attr_set) {
        cudaFuncSetAttribute(gemm_tc_kernel, cudaFuncAttributeMaxDynamicSharedMemorySize,
                             6 * STG_H * (int)sizeof(__half));
        attr_set = true;
    }

    // ---- one-time converts + CSR build ----
    cvt2h_kernel<<<(N_NODES * DIM / 4 + 255) / 256, 256>>>(xa_in, xp_in, xa16, xp16,
                                                           N_NODES * DIM / 4);
    cvt2h_kernel<<<(W_ELEMS / 4 + 255) / 256, 256>>>(Wl, Wr, hWl, hWr, W_ELEMS / 4);
    cudaMemsetAsync(degA, 0, N_NODES * sizeof(int));
    cudaMemsetAsync(degP, 0, N_NODES * sizeof(int));
    {
        dim3 g((N_EDGES + 255) / 256, 2);
        deg2_kernel<<<g, 256>>>(e_ap + N_EDGES, degP, e_pa + N_EDGES, degA, N_EDGES);
    }
    scan2_kernel<<<2, 1024>>>(degP, offP, degA, offA, N_NODES);
    cudaMemcpyAsync(curP, offP, N_NODES * sizeof(int), cudaMemcpyDeviceToDevice);
    cudaMemcpyAsync(curA, offA, N_NODES * sizeof(int), cudaMemcpyDeviceToDevice);
    {
        dim3 g((N_EDGES + 255) / 256, 2);
        fill2_kernel<<<g, 256>>>(e_ap, curP, csrP, e_pa, curA, csrA, N_EDGES);
    }

    const __half* inA = xa16;
    const __half* inP = xp16;

    dim3 gGrid(DIM / 128, (N_NODES + 127) / 128, 2);   // (2, 391, 2)
    dim3 wGrid((N_NODES + 7) / 8, 2);
    const int smemBytes = 6 * STG_H * (int)sizeof(__half);   // 48KB

    for (int l = 0; l < N_LAYERS; l++) {
        const bool last = (l == N_LAYERS - 1);
        __half* outA = last ? nullptr : bufA[l & 1];
        __half* outP = last ? nullptr : bufP[l & 1];

        gather2_kernel<<<wGrid, 256>>>(inA, offP, csrP, aggP,
                                       inP, offA, csrA, aggA, N_NODES);

        GemmArgs gp, ga;
        gp.agg = aggP; gp.self_ = inP;
        gp.wl = hWl + ((size_t)l * 2 + 0) * DIM * DIM;
        gp.wr = hWr + ((size_t)l * 2 + 0) * DIM * DIM;
        gp.bias = bl + ((size_t)l * 2 + 0) * DIM;
        gp.outH = outP;
        gp.outF = last ? out + (size_t)N_NODES * DIM : nullptr;
        ga.agg = aggA; ga.self_ = inA;
        ga.wl = hWl + ((size_t)l * 2 + 1) * DIM * DIM;
        ga.wr = hWr + ((size_t)l * 2 + 1) * DIM * DIM;
        ga.bias = bl + ((size_t)l * 2 + 1) * DIM;
        ga.outH = outA;
        ga.outF = last ? out : nullptr;

        gemm_tc_kernel<<<gGrid, 256, smemBytes>>>(gp, ga, N_NODES);

        if (!last)
            norm_relu2_kernel<<<wGrid, 256>>>(outP, outA, N_NODES);

        inA = outA;
        inP = outP;
    }
}

// round 8
// speedup vs baseline: 2.2800x; 1.0844x over previous
#include <cuda_runtime.h>
#include <cuda_fp16.h>
#include <cstdint>
#include <cstddef>

#define N_NODES 50000
#define DIM 256
#define N_EDGES 800000
#define N_LAYERS 5
#define W_ELEMS (N_LAYERS * 2 * DIM * DIM)   // 655360 per tensor

#define SCHUNK 512
#define SNB ((N_NODES + SCHUNK - 1) / SCHUNK)   // 98 blocks per direction

// ---------------- device scratch (allocation-free: .bss globals) ----------------
__device__ __half g_xa16[N_NODES * DIM];
__device__ __half g_xp16[N_NODES * DIM];
__device__ __half g_bufA0[N_NODES * DIM];
__device__ __half g_bufA1[N_NODES * DIM];
__device__ __half g_bufP0[N_NODES * DIM];
__device__ __half g_bufP1[N_NODES * DIM];
__device__ __half g_aggA[N_NODES * DIM];
__device__ __half g_aggP[N_NODES * DIM];
__device__ __half g_hWl[W_ELEMS];
__device__ __half g_hWr[W_ELEMS];
__device__ int    g_degA[N_NODES];
__device__ int    g_degP[N_NODES];
__device__ int    g_offA[N_NODES + 1];
__device__ int    g_offP[N_NODES + 1];
__device__ int    g_curA[N_NODES];
__device__ int    g_curP[N_NODES];
__device__ int    g_csrA[N_EDGES];
__device__ int    g_csrP[N_EDGES];
__device__ int    g_part[2][SNB];

// ---------------- fp32 -> fp16 convert (two tensors per launch) ----------------
__global__ void cvt2h_kernel(const float* __restrict__ a, const float* __restrict__ b,
                             __half* __restrict__ ah, __half* __restrict__ bh, int n4) {
    int i = blockIdx.x * blockDim.x + threadIdx.x;
    if (i < n4) {
        float4 va = reinterpret_cast<const float4*>(a)[i];
        float4 vb = reinterpret_cast<const float4*>(b)[i];
        reinterpret_cast<__half2*>(ah)[i * 2]     = __floats2half2_rn(va.x, va.y);
        reinterpret_cast<__half2*>(ah)[i * 2 + 1] = __floats2half2_rn(va.z, va.w);
        reinterpret_cast<__half2*>(bh)[i * 2]     = __floats2half2_rn(vb.x, vb.y);
        reinterpret_cast<__half2*>(bh)[i * 2 + 1] = __floats2half2_rn(vb.z, vb.w);
    }
}

// ---------------- CSR build: degree count (both directions, grid.y=2) ----------------
__global__ void deg2_kernel(const int* __restrict__ dstP, int* __restrict__ degP,
                            const int* __restrict__ dstA, int* __restrict__ degA, int E) {
    int e = blockIdx.x * blockDim.x + threadIdx.x;
    if (e < E) {
        if (blockIdx.y == 0) atomicAdd(&degP[dstP[e]], 1);
        else                 atomicAdd(&degA[dstA[e]], 1);
    }
}

// ---------------- parallel scan phase 1: per-block partial sums ----------------
__global__ void scan_p1(const int* __restrict__ dP, const int* __restrict__ dA, int n) {
    const int* deg = blockIdx.y ? dA : dP;
    const int tid = threadIdx.x;                 // 256
    int i0 = blockIdx.x * SCHUNK + tid * 2;
    int v = 0;
    if (i0 < n)     v += deg[i0];
    if (i0 + 1 < n) v += deg[i0 + 1];
    __shared__ int ws[8];
#pragma unroll
    for (int o = 16; o; o >>= 1) v += __shfl_xor_sync(0xFFFFFFFFu, v, o);
    if ((tid & 31) == 0) ws[tid >> 5] = v;
    __syncthreads();
    if (tid == 0) {
        int s = 0;
#pragma unroll
        for (int w = 0; w < 8; w++) s += ws[w];
        g_part[blockIdx.y][blockIdx.x] = s;
    }
}

// ---------------- phase 2: scan the 98 partials (one tiny block per direction) ----------
__global__ void scan_p2(int* __restrict__ offP, int* __restrict__ offA, int n) {
    const int dir = blockIdx.x;
    int* off = dir ? offA : offP;
    const int tid = threadIdx.x;                 // 128
    int v = (tid < SNB) ? g_part[dir][tid] : 0;
    __shared__ int ws[4];
    int x = v;
    const int lane = tid & 31, wid = tid >> 5;
#pragma unroll
    for (int o = 1; o < 32; o <<= 1) {
        int y = __shfl_up_sync(0xFFFFFFFFu, x, o);
        if (lane >= o) x += y;
    }
    if (lane == 31) ws[wid] = x;
    __syncthreads();
    if (tid < 4) {
        int w = ws[tid];
#pragma unroll
        for (int o = 1; o < 4; o <<= 1) {
            int y = __shfl_up_sync(0xFu, w, o);
            if (tid >= o) w += y;
        }
        ws[tid] = w;
    }
    __syncthreads();
    int incl = x + (wid ? ws[wid - 1] : 0);
    if (tid < SNB) g_part[dir][tid] = incl - v;   // exclusive block prefix
    if (tid == 127) off[n] = incl;                // grand total
}

// ---------------- phase 3: write offsets + cursors ----------------
__global__ void scan_p3(const int* __restrict__ dP, const int* __restrict__ dA,
                        int* __restrict__ offP, int* __restrict__ curP,
                        int* __restrict__ offA, int* __restrict__ curA, int n) {
    const int dir = blockIdx.y;
    const int* deg = dir ? dA : dP;
    int* off = dir ? offA : offP;
    int* cur = dir ? curA : curP;
    const int tid = threadIdx.x;                 // 256
    const int base = g_part[dir][blockIdx.x];
    int i0 = blockIdx.x * SCHUNK + tid * 2;
    int v0 = (i0 < n) ? deg[i0] : 0;
    int v1 = (i0 + 1 < n) ? deg[i0 + 1] : 0;
    int sum = v0 + v1;

    __shared__ int ws[8];
    int x = sum;
    const int lane = tid & 31, wid = tid >> 5;
#pragma unroll
    for (int o = 1; o < 32; o <<= 1) {
        int y = __shfl_up_sync(0xFFFFFFFFu, x, o);
        if (lane >= o) x += y;
    }
    if (lane == 31) ws[wid] = x;
    __syncthreads();
    if (tid < 8) {
        int w = ws[tid];
#pragma unroll
        for (int o = 1; o < 8; o <<= 1) {
            int y = __shfl_up_sync(0xFFu, w, o);
            if (tid >= o) w += y;
        }
        ws[tid] = w;
    }
    __syncthreads();
    int excl = x - sum + (wid ? ws[wid - 1] : 0);
    int p = base + excl;
    if (i0 < n)     { off[i0] = p;          cur[i0] = p; }
    if (i0 + 1 < n) { off[i0 + 1] = p + v0; cur[i0 + 1] = p + v0; }
}

// ---------------- CSR build: slot fill (both directions, grid.y=2) ----------------
__global__ void fill2_kernel(const int* __restrict__ eap, int* __restrict__ curP, int* __restrict__ csrP,
                             const int* __restrict__ epa, int* __restrict__ curA, int* __restrict__ csrA,
                             int E) {
    int e = blockIdx.x * blockDim.x + threadIdx.x;
    if (e < E) {
        if (blockIdx.y == 0) {
            int slot = atomicAdd(&curP[eap[E + e]], 1);
            csrP[slot] = eap[e];
        } else {
            int slot = atomicAdd(&curA[epa[E + e]], 1);
            csrA[slot] = epa[e];
        }
    }
}

// ---------------- gather (fp16 rows; both directions in one launch via grid.y) ----------------
__global__ void gather2_kernel(const __half* __restrict__ xA, const int* __restrict__ offP,
                               const int* __restrict__ csrP, __half* __restrict__ aggP,
                               const __half* __restrict__ xP, const int* __restrict__ offA,
                               const int* __restrict__ csrA, __half* __restrict__ aggA,
                               int n) {
    int row = blockIdx.x * (blockDim.x >> 5) + (threadIdx.x >> 5);
    if (row >= n) return;
    const int lane = threadIdx.x & 31;
    const __half* x;
    const int *off, *csr;
    __half* agg;
    if (blockIdx.y == 0) { x = xA; off = offP; csr = csrP; agg = aggP; }
    else                 { x = xP; off = offA; csr = csrA; agg = aggA; }
    const int beg = off[row], end = off[row + 1];

    float s[8] = {0.f, 0.f, 0.f, 0.f, 0.f, 0.f, 0.f, 0.f};
    int e = beg;
    for (; e + 1 < end; e += 2) {
        int i0 = csr[e], i1 = csr[e + 1];
        uint4 v0 = reinterpret_cast<const uint4*>(x + (size_t)i0 * DIM)[lane];
        uint4 v1 = reinterpret_cast<const uint4*>(x + (size_t)i1 * DIM)[lane];
        const __half2* h0 = reinterpret_cast<const __half2*>(&v0);
        const __half2* h1 = reinterpret_cast<const __half2*>(&v1);
#pragma unroll
        for (int j = 0; j < 4; j++) {
            float2 f0 = __half22float2(h0[j]);
            float2 f1 = __half22float2(h1[j]);
            s[j * 2]     += f0.x + f1.x;
            s[j * 2 + 1] += f0.y + f1.y;
        }
    }
    if (e < end) {
        uint4 v0 = reinterpret_cast<const uint4*>(x + (size_t)csr[e] * DIM)[lane];
        const __half2* h0 = reinterpret_cast<const __half2*>(&v0);
#pragma unroll
        for (int j = 0; j < 4; j++) {
            float2 f0 = __half22float2(h0[j]);
            s[j * 2]     += f0.x;
            s[j * 2 + 1] += f0.y;
        }
    }
    const float inv = 1.0f / fmaxf((float)(end - beg), 1.0f);
    uint4 o;
    __half2* ho = reinterpret_cast<__half2*>(&o);
#pragma unroll
    for (int j = 0; j < 4; j++)
        ho[j] = __floats2half2_rn(s[j * 2] * inv, s[j * 2 + 1] * inv);
    reinterpret_cast<uint4*>(agg + (size_t)row * DIM)[lane] = o;
}

// ---------------- fp16 tensor-core fused dual GEMM (ldmatrix fragments) ----------------
// out = agg @ Wl^T + self @ Wr^T + b (fp32 accum). m16n8k16, BM=128, BN=128, BK=32,
// 3-stage cp.async, XOR-swizzled smem, LDSM.x4 fragment loads, warp tile 32x64.

struct GemmArgs {
    const __half *agg, *self_, *wl, *wr;
    const float* bias;
    float* outF;    // non-null on last layer
    __half* outH;   // non-null on hidden layers
};

__device__ __forceinline__ void cp_async16(void* smem, const void* gmem, bool pred) {
    uint32_t s = (uint32_t)__cvta_generic_to_shared(smem);
    int sz = pred ? 16 : 0;
    asm volatile("cp.async.cg.shared.global [%0], [%1], 16, %2;"
                 :: "r"(s), "l"(gmem), "r"(sz));
}

#define LDSM_X4(r0, r1, r2, r3, addr)                                     \
    asm volatile("ldmatrix.sync.aligned.m8n8.x4.shared.b16 "              \
                 "{%0,%1,%2,%3}, [%4];"                                   \
                 : "=r"(r0), "=r"(r1), "=r"(r2), "=r"(r3) : "r"(addr))

#define STG_H (128 * 32)   // halfs per tile per stage (8KB)

__global__ __launch_bounds__(256, 2)
void gemm_tc_kernel(GemmArgs g0, GemmArgs g1, int M) {
    extern __shared__ __half sm[];
    __half* As = sm;                 // [3][128][32] XOR-swizzled
    __half* Bs = sm + 3 * STG_H;

    const GemmArgs* G = blockIdx.z ? &g1 : &g0;
    const __half* Aagg = G->agg;
    const __half* Aself = G->self_;
    const __half* Wl = G->wl;
    const __half* Wr = G->wr;

    const int bm = blockIdx.y * 128;
    const int bn = blockIdx.x * 128;
    const int t = threadIdx.x;
    const int wid = t >> 5;
    const int lane = t & 31;
    const int wm = wid & 3;
    const int wn = wid >> 2;
    const int gid = lane >> 2;
    const int tig = lane & 3;

    const uint32_t smem_u32 = (uint32_t)__cvta_generic_to_shared(sm);
    const uint32_t baseA = smem_u32;
    const uint32_t baseB = smem_u32 + 3 * STG_H * 2;

    // ldmatrix per-lane source descriptors (byte offsets within a stage)
    const int matq = lane >> 3;     // which 8x8 matrix this lane's address feeds
    const int rq = lane & 7;        // row within that matrix
    const int kselA = matq >> 1;    // A: mats 0,1 -> k-group +0; mats 2,3 -> +1
    uint32_t rowA[2]; int swA[2];
#pragma unroll
    for (int mi = 0; mi < 2; mi++) {
        int row = wm * 32 + mi * 16 + (matq & 1) * 8 + rq;
        rowA[mi] = row * 64;              // 64 bytes per smem row
        swA[mi] = (row >> 1) & 3;
    }
    const int kselB = matq & 1;     // B: mats 0,2 -> +0; mats 1,3 -> +1
    uint32_t rowB[4]; int swB[4];
#pragma unroll
    for (int j = 0; j < 4; j++) {
        int ni = 2 * j + (matq >> 1);
        int row = wn * 64 + ni * 8 + rq;
        rowB[j] = row * 64;
        swB[j] = (row >> 1) & 3;
    }

    float acc[2][8][4];
#pragma unroll
    for (int mi = 0; mi < 2; mi++)
#pragma unroll
        for (int ni = 0; ni < 8; ni++)
#pragma unroll
            for (int j = 0; j < 4; j++) acc[mi][ni][j] = 0.0f;

    // 16 k-tiles of 32: kt 0..7 phase 0 (agg,Wl), kt 8..15 phase 1 (self,Wr)
    auto load_tile = [&](int stage, int kt) {
        const int phase = kt >> 3;
        const int kloc = (kt & 7) << 5;
        const __half* Ap = phase ? Aself : Aagg;
        const __half* Bp = phase ? Wr : Wl;
        __half* as = As + stage * STG_H;
        __half* bs = Bs + stage * STG_H;
#pragma unroll
        for (int i = 0; i < 2; i++) {
            int c = t + i * 256;          // 0..511
            int row = c >> 2;
            int seg = c & 3;
            int segp = seg ^ ((row >> 1) & 3);
            int gr = bm + row;
            cp_async16(as + row * 32 + segp * 8,
                       Ap + (size_t)gr * DIM + kloc + seg * 8, gr < M);
            cp_async16(bs + row * 32 + segp * 8,
                       Bp + (size_t)(bn + row) * DIM + kloc + seg * 8, true);
        }
        asm volatile("cp.async.commit_group;" ::: "memory");
    };

    load_tile(0, 0);
    load_tile(1, 1);

#pragma unroll 1
    for (int kt = 0; kt < 16; kt++) {
        const int s = kt % 3;
        asm volatile("cp.async.wait_group 1;" ::: "memory");
        __syncthreads();
        if (kt + 2 < 16) load_tile((kt + 2) % 3, kt + 2);

        const uint32_t sA = baseA + s * (STG_H * 2);
        const uint32_t sB = baseB + s * (STG_H * 2);

#pragma unroll
        for (int ks = 0; ks < 2; ks++) {      // two m16n8k16 steps within BK=32
            const int gA = ks * 2;
            uint32_t aR[2][4];
#pragma unroll
            for (int mi = 0; mi < 2; mi++) {
                uint32_t addr = sA + rowA[mi] + (uint32_t)(((gA + kselA) ^ swA[mi]) << 4);
                LDSM_X4(aR[mi][0], aR[mi][1], aR[mi][2], aR[mi][3], addr);
            }
            uint32_t bR[8][2];
#pragma unroll
            for (int j = 0; j < 4; j++) {
                uint32_t addr = sB + rowB[j] + (uint32_t)(((gA + kselB) ^ swB[j]) << 4);
                LDSM_X4(bR[2 * j][0], bR[2 * j][1], bR[2 * j + 1][0], bR[2 * j + 1][1], addr);
            }
#pragma unroll
            for (int mi = 0; mi < 2; mi++)
#pragma unroll
                for (int ni = 0; ni < 8; ni++) {
                    asm volatile(
                        "mma.sync.aligned.m16n8k16.row.col.f32.f16.f16.f32 "
                        "{%0,%1,%2,%3}, {%4,%5,%6,%7}, {%8,%9}, {%0,%1,%2,%3};"
                        : "+f"(acc[mi][ni][0]), "+f"(acc[mi][ni][1]),
                          "+f"(acc[mi][ni][2]), "+f"(acc[mi][ni][3])
                        : "r"(aR[mi][0]), "r"(aR[mi][1]), "r"(aR[mi][2]), "r"(aR[mi][3]),
                          "r"(bR[ni][0]), "r"(bR[ni][1]));
                }
        }
    }

    const float* bias = G->bias;
    float* outF = G->outF;
    __half* outH = G->outH;
#pragma unroll
    for (int ni = 0; ni < 8; ni++) {
        int col = bn + wn * 64 + ni * 8 + 2 * tig;
        float bx = bias[col], by = bias[col + 1];
#pragma unroll
        for (int mi = 0; mi < 2; mi++) {
            int r0 = bm + wm * 32 + mi * 16 + gid;
            float ox0 = acc[mi][ni][0] + bx, oy0 = acc[mi][ni][1] + by;
            float ox1 = acc[mi][ni][2] + bx, oy1 = acc[mi][ni][3] + by;
            if (outH) {
                if (r0 < M)
                    *reinterpret_cast<__half2*>(outH + (size_t)r0 * DIM + col) =
                        __floats2half2_rn(ox0, oy0);
                if (r0 + 8 < M)
                    *reinterpret_cast<__half2*>(outH + (size_t)(r0 + 8) * DIM + col) =
                        __floats2half2_rn(ox1, oy1);
            } else {
                if (r0 < M)
                    *reinterpret_cast<float2*>(outF + (size_t)r0 * DIM + col) =
                        make_float2(ox0, oy0);
                if (r0 + 8 < M)
                    *reinterpret_cast<float2*>(outF + (size_t)(r0 + 8) * DIM + col) =
                        make_float2(ox1, oy1);
            }
        }
    }
}

// ---------------- L2 normalize + ReLU (fp16 rows, both matrices, grid.y=2) ----------------
__global__ void norm_relu2_kernel(__half* __restrict__ xP, __half* __restrict__ xA, int n) {
    int row = blockIdx.x * (blockDim.x >> 5) + (threadIdx.x >> 5);
    if (row >= n) return;
    __half* x = blockIdx.y ? xA : xP;
    int lane = threadIdx.x & 31;
    uint4 v = reinterpret_cast<uint4*>(x + (size_t)row * DIM)[lane];
    __half2* h = reinterpret_cast<__half2*>(&v);
    float f[8];
    float s = 0.f;
#pragma unroll
    for (int j = 0; j < 4; j++) {
        float2 p = __half22float2(h[j]);
        f[j * 2] = p.x; f[j * 2 + 1] = p.y;
        s += p.x * p.x + p.y * p.y;
    }
#pragma unroll
    for (int o = 16; o; o >>= 1) s += __shfl_xor_sync(0xFFFFFFFFu, s, o);
    float inv = 1.0f / fmaxf(sqrtf(s), 1e-12f);
    uint4 ov;
    __half2* ho = reinterpret_cast<__half2*>(&ov);
#pragma unroll
    for (int j = 0; j < 4; j++)
        ho[j] = __floats2half2_rn(fmaxf(f[j * 2] * inv, 0.f), fmaxf(f[j * 2 + 1] * inv, 0.f));
    reinterpret_cast<uint4*>(x + (size_t)row * DIM)[lane] = ov;
}

// ---------------- host orchestration ----------------
extern "C" void kernel_launch(void* const* d_in, const int* in_sizes, int n_in,
                              void* d_out, int out_size) {
    (void)in_sizes; (void)n_in; (void)out_size;
    const float* xa_in = (const float*)d_in[0];
    const float* xp_in = (const float*)d_in[1];
    const float* Wl    = (const float*)d_in[2];
    const float* bl    = (const float*)d_in[3];
    const float* Wr    = (const float*)d_in[4];
    const int*   e_ap  = (const int*)d_in[5];
    const int*   e_pa  = (const int*)d_in[6];
    float* out = (float*)d_out;

    __half *xa16, *xp16, *bufA[2], *bufP[2], *aggA, *aggP, *hWl, *hWr;
    int *degA, *degP, *offA, *offP, *curA, *curP, *csrA, *csrP;
    cudaGetSymbolAddress((void**)&xa16, g_xa16);
    cudaGetSymbolAddress((void**)&xp16, g_xp16);
    cudaGetSymbolAddress((void**)&bufA[0], g_bufA0);
    cudaGetSymbolAddress((void**)&bufA[1], g_bufA1);
    cudaGetSymbolAddress((void**)&bufP[0], g_bufP0);
    cudaGetSymbolAddress((void**)&bufP[1], g_bufP1);
    cudaGetSymbolAddress((void**)&aggA, g_aggA);
    cudaGetSymbolAddress((void**)&aggP, g_aggP);
    cudaGetSymbolAddress((void**)&hWl, g_hWl);
    cudaGetSymbolAddress((void**)&hWr, g_hWr);
    cudaGetSymbolAddress((void**)&degA, g_degA);
    cudaGetSymbolAddress((void**)&degP, g_degP);
    cudaGetSymbolAddress((void**)&offA, g_offA);
    cudaGetSymbolAddress((void**)&offP, g_offP);
    cudaGetSymbolAddress((void**)&curA, g_curA);
    cudaGetSymbolAddress((void**)&curP, g_curP);
    cudaGetSymbolAddress((void**)&csrA, g_csrA);
    cudaGetSymbolAddress((void**)&csrP, g_csrP);

    static bool attr_set = false;
    if (!attr_set) {
        cudaFuncSetAttribute(gemm_tc_kernel, cudaFuncAttributeMaxDynamicSharedMemorySize,
                             6 * STG_H * (int)sizeof(__half));
        attr_set = true;
    }

    // ---- one-time converts + CSR build ----
    cvt2h_kernel<<<(N_NODES * DIM / 4 + 255) / 256, 256>>>(xa_in, xp_in, xa16, xp16,
                                                           N_NODES * DIM / 4);
    cvt2h_kernel<<<(W_ELEMS / 4 + 255) / 256, 256>>>(Wl, Wr, hWl, hWr, W_ELEMS / 4);
    cudaMemsetAsync(degA, 0, N_NODES * sizeof(int));
    cudaMemsetAsync(degP, 0, N_NODES * sizeof(int));
    {
        dim3 g((N_EDGES + 255) / 256, 2);
        deg2_kernel<<<g, 256>>>(e_ap + N_EDGES, degP, e_pa + N_EDGES, degA, N_EDGES);
    }
    {
        dim3 g(SNB, 2);
        scan_p1<<<g, 256>>>(degP, degA, N_NODES);
        scan_p2<<<2, 128>>>(offP, offA, N_NODES);
        scan_p3<<<g, 256>>>(degP, degA, offP, curP, offA, curA, N_NODES);
    }
    {
        dim3 g((N_EDGES + 255) / 256, 2);
        fill2_kernel<<<g, 256>>>(e_ap, curP, csrP, e_pa, curA, csrA, N_EDGES);
    }

    const __half* inA = xa16;
    const __half* inP = xp16;

    dim3 gGrid(DIM / 128, (N_NODES + 127) / 128, 2);   // (2, 391, 2)
    dim3 wGrid((N_NODES + 7) / 8, 2);
    const int smemBytes = 6 * STG_H * (int)sizeof(__half);   // 48KB

    for (int l = 0; l < N_LAYERS; l++) {
        const bool last = (l == N_LAYERS - 1);
        __half* outA = last ? nullptr : bufA[l & 1];
        __half* outP = last ? nullptr : bufP[l & 1];

        gather2_kernel<<<wGrid, 256>>>(inA, offP, csrP, aggP,
                                       inP, offA, csrA, aggA, N_NODES);

        GemmArgs gp, ga;
        gp.agg = aggP; gp.self_ = inP;
        gp.wl = hWl + ((size_t)l * 2 + 0) * DIM * DIM;
        gp.wr = hWr + ((size_t)l * 2 + 0) * DIM * DIM;
        gp.bias = bl + ((size_t)l * 2 + 0) * DIM;
        gp.outH = outP;
        gp.outF = last ? out + (size_t)N_NODES * DIM : nullptr;
        ga.agg = aggA; ga.self_ = inA;
        ga.wl = hWl + ((size_t)l * 2 + 1) * DIM * DIM;
        ga.wr = hWr + ((size_t)l * 2 + 1) * DIM * DIM;
        ga.bias = bl + ((size_t)l * 2 + 1) * DIM;
        ga.outH = outA;
        ga.outF = last ? out : nullptr;

        gemm_tc_kernel<<<gGrid, 256, smemBytes>>>(gp, ga, N_NODES);

        if (!last)
            norm_relu2_kernel<<<wGrid, 256>>>(outP, outA, N_NODES);

        inA = outA;
        inP = outP;
    }
}